// round 13
// baseline (speedup 1.0000x reference)
#include <cuda_runtime.h>
#include <cuda_bf16.h>
#include <cuda_fp16.h>
#include <cstdint>

// B=4, S=1024, E=1024, H=16, D=64, BH=64.
// R9 structure (624.7us champion). Single delta: k3 processes 2 t-chunks per
// block (grid 4096), q tile loaded once, same smem footprint/occupancy.

#define DI __device__ __forceinline__

// ---------------- device scratch ----------------
__device__ __align__(128) __half g_we[67108864];                // fp16 edge logits [s][bh][t]
__device__ __align__(128) __half g_wf[67108864];                // fp16 softmax weights [s][bh][t]
__device__ __align__(128) float g_att[4194304];                 // fp32 PV partial att [b*s][h*d]
__device__ __align__(128) __half g_xf[3*4194304];               // X fp16 [z][m][k]
__device__ __align__(128) __half g_wtf[4*1048576];              // W^T fp16 [mat][n][k]
__device__ __align__(128) __half g_qf[4194304];                 // [bh][s][d] scaled q
__device__ __align__(128) __half g_kf[4194304];                 // [bh][t][d]
__device__ __align__(128) __half g_vf[4194304];                 // [bh][s][d]
__device__ __align__(128) __half g_vtf[4194304];                // [bh][d][t]
__device__ __align__(128) __half g_attf[4194304];               // final att fp16 [b*s][h*d]

// ---------------- helpers ----------------
union HF2 { __half b[2]; uint32_t u; };
union HF4 { __half b[4]; uint2 u; };

DI uint32_t smem_u32(const void* p) {
    uint32_t a;
    asm("{ .reg .u64 t; cvta.to.shared.u64 t, %1; cvt.u32.u64 %0, t; }" : "=r"(a) : "l"(p));
    return a;
}
DI void ldsm4(uint32_t* r, uint32_t a) {
    asm volatile("ldmatrix.sync.aligned.m8n8.x4.shared.b16 {%0,%1,%2,%3}, [%4];"
        : "=r"(r[0]), "=r"(r[1]), "=r"(r[2]), "=r"(r[3]) : "r"(a));
}
DI void ldsm4t(uint32_t* r, uint32_t a) {
    asm volatile("ldmatrix.sync.aligned.m8n8.x4.trans.shared.b16 {%0,%1,%2,%3}, [%4];"
        : "=r"(r[0]), "=r"(r[1]), "=r"(r[2]), "=r"(r[3]) : "r"(a));
}
DI void mma16816h(float* d, const uint32_t* a, const uint32_t* b) {
    asm volatile("mma.sync.aligned.m16n8k16.row.col.f32.f16.f16.f32 "
        "{%0,%1,%2,%3}, {%4,%5,%6,%7}, {%8,%9}, {%0,%1,%2,%3};"
        : "+f"(d[0]), "+f"(d[1]), "+f"(d[2]), "+f"(d[3])
        : "r"(a[0]), "r"(a[1]), "r"(a[2]), "r"(a[3]), "r"(b[0]), "r"(b[1]));
}
DI void cp16(uint32_t d, const void* s) {
    asm volatile("cp.async.cg.shared.global [%0], [%1], 16;" :: "r"(d), "l"(s));
}
DI void cp_commit() { asm volatile("cp.async.commit_group;" ::: "memory"); }
template <int N> DI void cp_wait() {
    asm volatile("cp.async.wait_group %0;" :: "n"(N) : "memory");
}

template <int ROWS, int KC, typename T>
DI void cp_one(uint32_t s, const T* G, size_t ldg) {
    constexpr int SA = KC + 8;
#pragma unroll
    for (int i = threadIdx.x; i < ROWS * KC / 8; i += 256) {
        int r = i / (KC / 8), c = (i % (KC / 8)) * 8;
        cp16(s + (uint32_t)(r * SA + c) * 2, G + (size_t)r * ldg + c);
    }
}
template <int ROWS, int KC, typename T>
DI void load_one(char* s, const T* G, size_t ldg) {
    constexpr int SA = KC + 8;
#pragma unroll 4
    for (int i = threadIdx.x; i < ROWS * KC / 8; i += 256) {
        int r = i / (KC / 8), c = (i % (KC / 8)) * 8;
        *(uint4*)(s + (r * SA + c) * 2) = *(const uint4*)(G + (size_t)r * ldg + c);
    }
}
template <int ROWS, int KC>
DI void load_cvt_h(char* s, const float* G, size_t ldg) {
    constexpr int SA = KC + 8;
#pragma unroll 4
    for (int i = threadIdx.x; i < ROWS * KC / 4; i += 256) {
        int r = i / (KC / 4), c = (i % (KC / 4)) * 4;
        float4 v = *(const float4*)(G + (size_t)r * ldg + c);
        HF4 Hh;
        Hh.b[0] = __float2half_rn(v.x); Hh.b[1] = __float2half_rn(v.y);
        Hh.b[2] = __float2half_rn(v.z); Hh.b[3] = __float2half_rn(v.w);
        *(uint2*)(s + (r * SA + c) * 2) = Hh.u;
    }
}

// fp16 chunk: A single, B single -> 1 product
template <int WN, int MT, int NT, int SA, int SB, int KSTEPS, bool BT>
DI void mma_chunk_h1(uint32_t aF, uint32_t bF, float (&acc)[MT][NT][4]) {
    int lane = threadIdx.x & 31, wid = threadIdx.x >> 5;
    int wm = wid / WN, wn = wid % WN;
#pragma unroll
    for (int kk = 0; kk < KSTEPS; kk++) {
        uint32_t af[MT][4], bf[NT][2];
#pragma unroll
        for (int mt = 0; mt < MT; mt++) {
            uint32_t off = (uint32_t)(((wm * MT * 16 + mt * 16 + (lane & 15)) * SA
                                       + kk * 16 + (lane >> 4) * 8) * 2);
            ldsm4(af[mt], aF + off);
        }
#pragma unroll
        for (int nt = 0; nt < NT; nt += 2) {
            uint32_t off;
            if (BT)
                off = (uint32_t)(((kk * 16 + (lane & 15)) * SB
                                  + wn * NT * 8 + nt * 8 + (lane >> 4) * 8) * 2);
            else
                off = (uint32_t)(((wn * NT * 8 + nt * 8 + ((lane >> 4) << 3) + (lane & 7)) * SB
                                  + kk * 16 + (((lane >> 3) & 1) << 3)) * 2);
            uint32_t r[4];
            if (BT) ldsm4t(r, bF + off); else ldsm4(r, bF + off);
            bf[nt][0] = r[0]; bf[nt][1] = r[1]; bf[nt + 1][0] = r[2]; bf[nt + 1][1] = r[3];
        }
#pragma unroll
        for (int mt = 0; mt < MT; mt++)
#pragma unroll
            for (int nt = 0; nt < NT; nt++)
                mma16816h(acc[mt][nt], af[mt], bf[nt]);
    }
}

// ---------------- conversion kernels ----------------
__global__ __launch_bounds__(256) void c0_wt(const float* Wq, const float* Wk,
                                             const float* Wv, const float* Wp) {
    __shared__ float smt[32][33];
    int mat = blockIdx.z;
    const float* W = mat == 0 ? Wq : mat == 1 ? Wk : mat == 2 ? Wv : Wp;
    int nblk = blockIdx.x * 32, kblk = blockIdx.y * 32;
    for (int i = threadIdx.x; i < 1024; i += 256) {
        int r = i >> 5, c = i & 31;
        smt[r][c] = W[(size_t)(kblk + r) * 1024 + nblk + c];
    }
    __syncthreads();
    for (int i = threadIdx.x; i < 1024; i += 256) {
        int n = i >> 5, k = i & 31;
        size_t o = (size_t)mat * 1048576 + (size_t)(nblk + n) * 1024 + kblk + k;
        g_wtf[o] = __float2half_rn(smt[k][n]);
    }
}
__global__ __launch_bounds__(256) void c1_x(const float* q, const float* k, const float* v) {
    int z = blockIdx.y;
    const float* X = z == 0 ? q : z == 1 ? k : v;
    size_t idx = ((size_t)blockIdx.x * 256 + threadIdx.x) * 4;
    float4 t = *(const float4*)&X[idx];
    HF4 Hh;
    Hh.b[0] = __float2half_rn(t.x); Hh.b[1] = __float2half_rn(t.y);
    Hh.b[2] = __float2half_rn(t.z); Hh.b[3] = __float2half_rn(t.w);
    *(uint2*)&g_xf[(size_t)z * 4194304 + idx] = Hh.u;
}
__global__ __launch_bounds__(256) void c2_vt() {
    __shared__ __half smh[64][65];
    int sblk = blockIdx.x * 64, bh = blockIdx.y;
    size_t ibase = (size_t)bh * 65536;
    for (int i = threadIdx.x; i < 4096; i += 256) {
        int s = i >> 6, d = i & 63;
        smh[s][d] = g_vf[ibase + (size_t)(sblk + s) * 64 + d];
    }
    __syncthreads();
    for (int i = threadIdx.x; i < 4096; i += 256) {
        int d = i >> 6, s = i & 63;
        g_vtf[ibase + (size_t)d * 1024 + sblk + s] = smh[s][d];
    }
}

// ---------------- G1: q/k/v = X @ W^T + b (1 product, cp.async) ----------------
__global__ __launch_bounds__(256) void g1_qkv(const float* bq, const float* bk, const float* bv) {
    extern __shared__ char sm[];
    uint32_t smb = smem_u32(sm);
    constexpr int TS = 128 * 72 * 2;
    constexpr int STG = 2 * TS;
    int z = blockIdx.z, m0 = blockIdx.y * 128, n0 = blockIdx.x * 128;
    const __half* Af = g_xf + (size_t)z * 4194304 + (size_t)m0 * 1024;
    const __half* Bf = g_wtf + (size_t)z * 1048576 + (size_t)n0 * 1024;
    float acc[4][4][4] = {};
    auto issue = [&](int c) {
        uint32_t b = smb + (uint32_t)(c & 1) * STG;
        cp_one<128, 64>(b, Af + c * 64, 1024);
        cp_one<128, 64>(b + TS, Bf + c * 64, 1024);
        cp_commit();
    };
    issue(0);
    for (int c = 0; c < 16; c++) {
        if (c < 15) { issue(c + 1); cp_wait<1>(); } else cp_wait<0>();
        __syncthreads();
        uint32_t b = smb + (uint32_t)(c & 1) * STG;
        mma_chunk_h1<4, 4, 4, 72, 72, 4, false>(b, b + TS, acc);
        __syncthreads();
    }
    const float* bias = z == 0 ? bq : z == 1 ? bk : bv;
    float sc = z == 0 ? 0.125f : 1.f;
    __half* dst = z == 0 ? g_qf : z == 1 ? g_kf : g_vf;
    int lane = threadIdx.x & 31, wid = threadIdx.x >> 5, wm = wid / 4, wn = wid % 4;
#pragma unroll
    for (int mt = 0; mt < 4; mt++)
#pragma unroll
        for (int nt = 0; nt < 4; nt++)
#pragma unroll
            for (int hf = 0; hf < 2; hf++) {
                int m = m0 + wm * 64 + mt * 16 + (lane >> 2) + hf * 8;
                int n = n0 + wn * 32 + nt * 8 + (lane & 3) * 2;
                float v0 = (acc[mt][nt][hf * 2] + bias[n]) * sc;
                float v1 = (acc[mt][nt][hf * 2 + 1] + bias[n + 1]) * sc;
                int b = m >> 10, s = m & 1023, h = n >> 6, d = n & 63;
                size_t o = ((size_t)((b << 4) + h) * 1024 + s) * 64 + d;
                HF2 P;
                P.b[0] = __float2half_rn(v0); P.b[1] = __float2half_rn(v1);
                *(uint32_t*)&dst[o] = P.u;
            }
}

// ---------------- K3: g_we[s][bh][t] = fp16 edge-key logits ----------------
// 2 t-chunks of 128 per block; q loaded once. Same smem/regs as R9 k3.
__global__ __launch_bounds__(256) void k3_edge(const float* __restrict__ ek) {
    extern __shared__ char sm[];
    char *aF = sm, *bF = sm + 9216;
    uint32_t aFu = smem_u32(aF), bFu = smem_u32(bF);
    int s = blockIdx.y, t00 = blockIdx.x * 256;
    int lane = threadIdx.x & 31, wid = threadIdx.x >> 5, wm = wid / 4, wn = wid % 4;
    size_t sbase = (size_t)s * 65536;
    load_one<64, 64>(aF, g_qf + (size_t)s * 64, 65536);
#pragma unroll
    for (int ch = 0; ch < 2; ch++) {
        int t0 = t00 + ch * 128;
        load_cvt_h<128, 64>(bF, ek + (size_t)s * 65536 + (size_t)t0 * 64, 64);
        __syncthreads();
        float acc[2][4][4] = {};
        mma_chunk_h1<4, 2, 4, 72, 72, 4, false>(aFu, bFu, acc);
#pragma unroll
        for (int mt = 0; mt < 2; mt++)
#pragma unroll
            for (int nt = 0; nt < 4; nt++)
#pragma unroll
                for (int hf = 0; hf < 2; hf++) {
                    int bh = wm * 32 + mt * 16 + (lane >> 2) + hf * 8;
                    int t = t0 + wn * 32 + nt * 8 + (lane & 3) * 2;
                    HF2 P;
                    P.b[0] = __float2half_rn(acc[mt][nt][hf * 2]);
                    P.b[1] = __float2half_rn(acc[mt][nt][hf * 2 + 1]);
                    *(uint32_t*)&g_we[sbase + (size_t)bh * 1024 + t] = P.u;
                }
        __syncthreads();
    }
}

// ---------------- G2S: content + bias + edge + softmax -> fp16 w [s][bh][t] ----------------
__global__ __launch_bounds__(256) void g2s(const float* __restrict__ attn_bias) {
    extern __shared__ char sm[];
    __shared__ float red[8][32];
    __shared__ float redc[32];
    constexpr int KTS = 128 * 72 * 2;
    uint32_t smb = smem_u32(sm);
    uint32_t qFu = smb;
    int s0 = blockIdx.x * 32, bh = blockIdx.y;
    int tid = threadIdx.x, lane = tid & 31, wn = tid >> 5;

    auto issueK = [&](int it) {
        uint32_t b = smb + 4608 + (uint32_t)(it & 1) * KTS;
        cp_one<128, 64>(b, g_kf + (size_t)bh * 65536 + (size_t)it * 8192, 64);
        cp_commit();
    };
    issueK(0);
    load_one<32, 64>(sm, g_qf + (size_t)bh * 65536 + (size_t)s0 * 64, 64);

    float acc[2][16][4] = {};
    for (int it = 0; it < 8; it++) {
        if (it < 7) { issueK(it + 1); cp_wait<1>(); } else cp_wait<0>();
        __syncthreads();
        uint32_t kFu = smb + 4608 + (uint32_t)(it & 1) * KTS;
#pragma unroll
        for (int kk = 0; kk < 4; kk++) {
            uint32_t ah[2][4], bf2[2][2];
#pragma unroll
            for (int mt = 0; mt < 2; mt++) {
                uint32_t off = (uint32_t)(((mt * 16 + (lane & 15)) * 72
                                           + kk * 16 + (lane >> 4) * 8) * 2);
                ldsm4(ah[mt], qFu + off);
            }
            {
                uint32_t off = (uint32_t)(((wn * 16 + ((lane >> 4) << 3) + (lane & 7)) * 72
                                           + kk * 16 + (((lane >> 3) & 1) << 3)) * 2);
                uint32_t r[4];
                ldsm4(r, kFu + off);
                bf2[0][0] = r[0]; bf2[0][1] = r[1]; bf2[1][0] = r[2]; bf2[1][1] = r[3];
            }
#pragma unroll
            for (int mt = 0; mt < 2; mt++)
#pragma unroll
                for (int ntl = 0; ntl < 2; ntl++)
                    mma16816h(acc[mt][it * 2 + ntl], ah[mt], bf2[ntl]);
        }
        __syncthreads();
    }

    // stage g_we slab (coalesced) into smem, then add bias (fp32) + edge
    __half* stg = (__half*)sm;   // 32 x 1040
    for (int i = tid; i < 32 * 128; i += 256) {
        int rr = i >> 7, cc = (i & 127) * 8;
        *(uint4*)&stg[rr * 1040 + cc] =
            *(const uint4*)&g_we[(size_t)(s0 + rr) * 65536 + (size_t)bh * 1024 + cc];
    }
    __syncthreads();

    size_t bbase = (size_t)bh * 1048576;
#pragma unroll
    for (int mt = 0; mt < 2; mt++)
#pragma unroll
        for (int ntg = 0; ntg < 16; ntg++) {
            int sl = mt * 16 + (lane >> 2);
            int t = (ntg >> 1) * 128 + wn * 16 + (ntg & 1) * 8 + (lane & 3) * 2;
            float2 b0 = *(const float2*)&attn_bias[bbase + (size_t)(s0 + sl) * 1024 + t];
            float2 b1 = *(const float2*)&attn_bias[bbase + (size_t)(s0 + sl + 8) * 1024 + t];
            HF2 e0, e1;
            e0.u = *(const uint32_t*)&stg[sl * 1040 + t];
            e1.u = *(const uint32_t*)&stg[(sl + 8) * 1040 + t];
            acc[mt][ntg][0] += b0.x + __half2float(e0.b[0]);
            acc[mt][ntg][1] += b0.y + __half2float(e0.b[1]);
            acc[mt][ntg][2] += b1.x + __half2float(e1.b[0]);
            acc[mt][ntg][3] += b1.y + __half2float(e1.b[1]);
        }

    float rv[4];
#pragma unroll
    for (int r = 0; r < 4; r++) rv[r] = -1e30f;
#pragma unroll
    for (int mt = 0; mt < 2; mt++)
#pragma unroll
        for (int ntg = 0; ntg < 16; ntg++)
#pragma unroll
            for (int e = 0; e < 4; e++) {
                int r = mt * 2 + (e >> 1);
                rv[r] = fmaxf(rv[r], acc[mt][ntg][e]);
            }
#pragma unroll
    for (int r = 0; r < 4; r++) {
        rv[r] = fmaxf(rv[r], __shfl_xor_sync(~0u, rv[r], 1));
        rv[r] = fmaxf(rv[r], __shfl_xor_sync(~0u, rv[r], 2));
    }
    if ((lane & 3) == 0)
#pragma unroll
        for (int r = 0; r < 4; r++)
            red[wn][(r >> 1) * 16 + (lane >> 2) + (r & 1) * 8] = rv[r];
    __syncthreads();
    if (tid < 32) {
        float m = red[0][tid];
#pragma unroll
        for (int w = 1; w < 8; w++) m = fmaxf(m, red[w][tid]);
        redc[tid] = m;
    }
    __syncthreads();
    float rmax[4];
#pragma unroll
    for (int r = 0; r < 4; r++) rmax[r] = redc[(r >> 1) * 16 + (lane >> 2) + (r & 1) * 8];
    __syncthreads();

#pragma unroll
    for (int r = 0; r < 4; r++) rv[r] = 0.f;
#pragma unroll
    for (int mt = 0; mt < 2; mt++)
#pragma unroll
        for (int ntg = 0; ntg < 16; ntg++)
#pragma unroll
            for (int e = 0; e < 4; e++) {
                int r = mt * 2 + (e >> 1);
                float v = __expf(acc[mt][ntg][e] - rmax[r]);
                acc[mt][ntg][e] = v;
                rv[r] += v;
            }
#pragma unroll
    for (int r = 0; r < 4; r++) {
        rv[r] += __shfl_xor_sync(~0u, rv[r], 1);
        rv[r] += __shfl_xor_sync(~0u, rv[r], 2);
    }
    if ((lane & 3) == 0)
#pragma unroll
        for (int r = 0; r < 4; r++)
            red[wn][(r >> 1) * 16 + (lane >> 2) + (r & 1) * 8] = rv[r];
    __syncthreads();
    if (tid < 32) {
        float sval = red[0][tid];
#pragma unroll
        for (int w = 1; w < 8; w++) sval += red[w][tid];
        redc[tid] = 1.0f / sval;
    }
    __syncthreads();
    float rinv[4];
#pragma unroll
    for (int r = 0; r < 4; r++) rinv[r] = redc[(r >> 1) * 16 + (lane >> 2) + (r & 1) * 8];
    __syncthreads();

#pragma unroll
    for (int mt = 0; mt < 2; mt++)
#pragma unroll
        for (int ntg = 0; ntg < 16; ntg++) {
            int sl = mt * 16 + (lane >> 2);
            int t = (ntg >> 1) * 128 + wn * 16 + (ntg & 1) * 8 + (lane & 3) * 2;
            *(__half2*)&stg[sl * 1040 + t] =
                __floats2half2_rn(acc[mt][ntg][0] * rinv[mt * 2],
                                  acc[mt][ntg][1] * rinv[mt * 2]);
            *(__half2*)&stg[(sl + 8) * 1040 + t] =
                __floats2half2_rn(acc[mt][ntg][2] * rinv[mt * 2 + 1],
                                  acc[mt][ntg][3] * rinv[mt * 2 + 1]);
        }
    __syncthreads();
    for (int i = tid; i < 32 * 128; i += 256) {
        int rr = i >> 7, cc = (i & 127) * 8;
        *(uint4*)&g_wf[(size_t)(s0 + rr) * 65536 + (size_t)bh * 1024 + cc] =
            *(const uint4*)&stg[rr * 1040 + cc];
    }
}

// ---------------- G5: att = W @ V (1 product, cp.async) ----------------
__global__ __launch_bounds__(256) void g5_pv() {
    extern __shared__ char sm[];
    uint32_t smb = smem_u32(sm);
    constexpr int ATS = 128 * 72 * 2;
    constexpr int BTS = 64 * 72 * 2;
    constexpr int STG = ATS + BTS;
    int bh = blockIdx.y, m0 = blockIdx.x * 128;
    const __half* A = g_wf + (size_t)m0 * 65536 + (size_t)bh * 1024;
    const __half* Bf = g_vtf + (size_t)bh * 65536;
    float acc[2][4][4] = {};
    auto issue = [&](int c) {
        uint32_t b = smb + (uint32_t)(c & 1) * STG;
        cp_one<128, 64>(b, A + c * 64, 65536);
        cp_one<64, 64>(b + ATS, Bf + c * 64, 1024);
        cp_commit();
    };
    issue(0);
    for (int c = 0; c < 16; c++) {
        if (c < 15) { issue(c + 1); cp_wait<1>(); } else cp_wait<0>();
        __syncthreads();
        uint32_t b = smb + (uint32_t)(c & 1) * STG;
        mma_chunk_h1<2, 2, 4, 72, 72, 4, false>(b, b + ATS, acc);
        __syncthreads();
    }
    int lane = threadIdx.x & 31, wid = threadIdx.x >> 5, wm = wid / 2, wn = wid % 2;
    int b = bh >> 4, h = bh & 15;
#pragma unroll
    for (int mt = 0; mt < 2; mt++)
#pragma unroll
        for (int nt = 0; nt < 4; nt++)
#pragma unroll
            for (int hf = 0; hf < 2; hf++) {
                int s = m0 + wm * 32 + mt * 16 + (lane >> 2) + hf * 8;
                int d = wn * 32 + nt * 8 + (lane & 3) * 2;
                size_t o = ((size_t)(b * 1024 + s)) * 1024 + h * 64 + d;
                float2 vv;
                vv.x = acc[mt][nt][hf * 2];
                vv.y = acc[mt][nt][hf * 2 + 1];
                *(float2*)&g_att[o] = vv;
            }
}

// ---------------- K6: attf = att + W @ EV_s (pipelined ev stream) ----------------
__global__ __launch_bounds__(256) void k6_ev(const float* __restrict__ ev) {
    extern __shared__ char sm[];
    char *aF = sm, *bFh = sm + 17408;
    uint32_t aFu = smem_u32(aF), bFu = smem_u32(bFh);
    uint32_t brawu = smem_u32(sm + 35840);
    int s = blockIdx.x;
    const float* evs = ev + (size_t)s * 65536;
    float acc[1][4][4] = {};
    auto issueB = [&](int c) {
        uint32_t dst = brawu + (uint32_t)(c & 1) * 32768;
        const float* src = evs + (size_t)c * 8192;
#pragma unroll
        for (int i = threadIdx.x; i < 2048; i += 256)
            cp16(dst + (uint32_t)i * 16, src + i * 4);
        cp_commit();
    };
    issueB(0);
    for (int c = 0; c < 8; c++) {
        load_one<64, 128>(aF, g_wf + (size_t)s * 65536 + c * 128, 1024);
        if (c < 7) { issueB(c + 1); cp_wait<1>(); } else cp_wait<0>();
        __syncthreads();
        const float* bw = (const float*)(sm + 35840 + (c & 1) * 32768);
#pragma unroll
        for (int i = threadIdx.x; i < 2048; i += 256) {
            int r = i >> 4, cc = (i & 15) * 4;
            float4 v = *(const float4*)(bw + r * 64 + cc);
            HF4 Hh;
            Hh.b[0] = __float2half_rn(v.x); Hh.b[1] = __float2half_rn(v.y);
            Hh.b[2] = __float2half_rn(v.z); Hh.b[3] = __float2half_rn(v.w);
            *(uint2*)(bFh + (r * 72 + cc) * 2) = Hh.u;
        }
        __syncthreads();
        mma_chunk_h1<2, 1, 4, 136, 72, 8, true>(aFu, bFu, acc);
        __syncthreads();
    }
    int lane = threadIdx.x & 31, wid = threadIdx.x >> 5, wm = wid / 2, wn = wid % 2;
#pragma unroll
    for (int nt = 0; nt < 4; nt++)
#pragma unroll
        for (int hf = 0; hf < 2; hf++) {
            int bh = wm * 16 + (lane >> 2) + hf * 8;
            int d = wn * 32 + nt * 8 + (lane & 3) * 2;
            int b = bh >> 4, h = bh & 15;
            size_t o = ((size_t)(b * 1024 + s)) * 1024 + h * 64 + d;
            float2 cur = *(float2*)&g_att[o];
            HF2 P;
            P.b[0] = __float2half_rn(cur.x + acc[0][nt][hf * 2]);
            P.b[1] = __float2half_rn(cur.y + acc[0][nt][hf * 2 + 1]);
            *(uint32_t*)&g_attf[o] = P.u;
        }
}

// ---------------- G7: out = att @ Wp^T + bp (1 product, cp.async) ----------------
__global__ __launch_bounds__(256) void g7_out(const float* __restrict__ bp, float* __restrict__ out) {
    extern __shared__ char sm[];
    uint32_t smb = smem_u32(sm);
    constexpr int TS = 128 * 72 * 2;
    constexpr int STG = 2 * TS;
    int m0 = blockIdx.y * 128, n0 = blockIdx.x * 128;
    const __half* Bf = g_wtf + (size_t)3 * 1048576 + (size_t)n0 * 1024;
    float acc[4][4][4] = {};
    auto issue = [&](int c) {
        uint32_t b = smb + (uint32_t)(c & 1) * STG;
        cp_one<128, 64>(b, g_attf + (size_t)m0 * 1024 + c * 64, 1024);
        cp_one<128, 64>(b + TS, Bf + c * 64, 1024);
        cp_commit();
    };
    issue(0);
    for (int c = 0; c < 16; c++) {
        if (c < 15) { issue(c + 1); cp_wait<1>(); } else cp_wait<0>();
        __syncthreads();
        uint32_t b = smb + (uint32_t)(c & 1) * STG;
        mma_chunk_h1<4, 4, 4, 72, 72, 4, false>(b, b + TS, acc);
        __syncthreads();
    }
    int lane = threadIdx.x & 31, wid = threadIdx.x >> 5, wm = wid / 4, wn = wid % 4;
#pragma unroll
    for (int mt = 0; mt < 4; mt++)
#pragma unroll
        for (int nt = 0; nt < 4; nt++)
#pragma unroll
            for (int hf = 0; hf < 2; hf++) {
                int m = m0 + wm * 64 + mt * 16 + (lane >> 2) + hf * 8;
                int n = n0 + wn * 32 + nt * 8 + (lane & 3) * 2;
                float2 bb = *(const float2*)&bp[n];
                float2 vv;
                vv.x = acc[mt][nt][hf * 2] + bb.x;
                vv.y = acc[mt][nt][hf * 2 + 1] + bb.y;
                *(float2*)&out[(size_t)m * 1024 + n] = vv;
            }
}

// ---------------- launch ----------------
extern "C" void kernel_launch(void* const* d_in, const int* in_sizes, int n_in,
                              void* d_out, int out_size) {
    const float* queries     = (const float*)d_in[0];
    const float* keys        = (const float*)d_in[1];
    const float* values      = (const float*)d_in[2];
    const float* edges_key   = (const float*)d_in[3];
    const float* edges_value = (const float*)d_in[4];
    const float* attn_bias   = (const float*)d_in[5];
    const float* Wq = (const float*)d_in[6];  const float* bq = (const float*)d_in[7];
    const float* Wk = (const float*)d_in[8];  const float* bk = (const float*)d_in[9];
    const float* Wv = (const float*)d_in[10]; const float* bv = (const float*)d_in[11];
    const float* Wp = (const float*)d_in[12]; const float* bp = (const float*)d_in[13];

    cudaFuncSetAttribute(g1_qkv,  cudaFuncAttributeMaxDynamicSharedMemorySize, 73728);
    cudaFuncSetAttribute(k3_edge, cudaFuncAttributeMaxDynamicSharedMemorySize, 27648);
    cudaFuncSetAttribute(g2s,     cudaFuncAttributeMaxDynamicSharedMemorySize, 66560);
    cudaFuncSetAttribute(g5_pv,   cudaFuncAttributeMaxDynamicSharedMemorySize, 55296);
    cudaFuncSetAttribute(k6_ev,   cudaFuncAttributeMaxDynamicSharedMemorySize, 101376);
    cudaFuncSetAttribute(g7_out,  cudaFuncAttributeMaxDynamicSharedMemorySize, 73728);

    c0_wt<<<dim3(32, 32, 4), 256>>>(Wq, Wk, Wv, Wp);
    c1_x<<<dim3(4096, 3), 256>>>(queries, keys, values);
    g1_qkv<<<dim3(8, 32, 3), 256, 73728>>>(bq, bk, bv);
    c2_vt<<<dim3(16, 64), 256>>>();
    k3_edge<<<dim3(4, 1024), 256, 27648>>>(edges_key);
    g2s<<<dim3(32, 64), 256, 66560>>>(attn_bias);
    g5_pv<<<dim3(8, 64), 256, 55296>>>();
    k6_ev<<<1024, 256, 101376>>>(edges_value);
    g7_out<<<dim3(8, 32), 256, 73728>>>(bp, (float*)d_out);
}

// round 14
// speedup vs baseline: 1.0068x; 1.0068x over previous
#include <cuda_runtime.h>
#include <cuda_bf16.h>
#include <cuda_fp16.h>
#include <cstdint>

// B=4, S=1024, E=1024, H=16, D=64, BH=64.
// All GEMMs single-fp16 mma.sync m16n8k16, fp32 accum, cp.async pipelines.
// Edge logits + softmax weights stored fp16 in [s][bh][t] layout; attn_bias
// (fp32) added in g2s. No fp32 logits intermediate.  (R9 champion, re-bench.)

#define DI __device__ __forceinline__

// ---------------- device scratch ----------------
__device__ __align__(128) __half g_we[67108864];                // fp16 edge logits [s][bh][t]
__device__ __align__(128) __half g_wf[67108864];                // fp16 softmax weights [s][bh][t]
__device__ __align__(128) float g_att[4194304];                 // fp32 att [b*s][h*d]
__device__ __align__(128) __half g_xf[3*4194304];               // X fp16 [z][m][k]
__device__ __align__(128) __half g_wtf[4*1048576];              // W^T fp16 [mat][n][k]
__device__ __align__(128) __half g_qf[4194304];                 // [bh][s][d] scaled q
__device__ __align__(128) __half g_kf[4194304];                 // [bh][t][d]
__device__ __align__(128) __half g_vf[4194304];                 // [bh][s][d]
__device__ __align__(128) __half g_vtf[4194304];                // [bh][d][t]
__device__ __align__(128) __half g_attf[4194304];               // final att fp16 [b*s][h*d]

// ---------------- helpers ----------------
union HF2 { __half b[2]; uint32_t u; };
union HF4 { __half b[4]; uint2 u; };

DI uint32_t smem_u32(const void* p) {
    uint32_t a;
    asm("{ .reg .u64 t; cvta.to.shared.u64 t, %1; cvt.u32.u64 %0, t; }" : "=r"(a) : "l"(p));
    return a;
}
DI void ldsm4(uint32_t* r, uint32_t a) {
    asm volatile("ldmatrix.sync.aligned.m8n8.x4.shared.b16 {%0,%1,%2,%3}, [%4];"
        : "=r"(r[0]), "=r"(r[1]), "=r"(r[2]), "=r"(r[3]) : "r"(a));
}
DI void ldsm4t(uint32_t* r, uint32_t a) {
    asm volatile("ldmatrix.sync.aligned.m8n8.x4.trans.shared.b16 {%0,%1,%2,%3}, [%4];"
        : "=r"(r[0]), "=r"(r[1]), "=r"(r[2]), "=r"(r[3]) : "r"(a));
}
DI void mma16816h(float* d, const uint32_t* a, const uint32_t* b) {
    asm volatile("mma.sync.aligned.m16n8k16.row.col.f32.f16.f16.f32 "
        "{%0,%1,%2,%3}, {%4,%5,%6,%7}, {%8,%9}, {%0,%1,%2,%3};"
        : "+f"(d[0]), "+f"(d[1]), "+f"(d[2]), "+f"(d[3])
        : "r"(a[0]), "r"(a[1]), "r"(a[2]), "r"(a[3]), "r"(b[0]), "r"(b[1]));
}
DI void cp16(uint32_t d, const void* s) {
    asm volatile("cp.async.cg.shared.global [%0], [%1], 16;" :: "r"(d), "l"(s));
}
DI void cp_commit() { asm volatile("cp.async.commit_group;" ::: "memory"); }
template <int N> DI void cp_wait() {
    asm volatile("cp.async.wait_group %0;" :: "n"(N) : "memory");
}

// cp.async single tile: ROWS x KC 16-bit -> padded smem (stride KC+8)
template <int ROWS, int KC, typename T>
DI void cp_one(uint32_t s, const T* G, size_t ldg) {
    constexpr int SA = KC + 8;
#pragma unroll
    for (int i = threadIdx.x; i < ROWS * KC / 8; i += 256) {
        int r = i / (KC / 8), c = (i % (KC / 8)) * 8;
        cp16(s + (uint32_t)(r * SA + c) * 2, G + (size_t)r * ldg + c);
    }
}
// synchronous single 16-bit tile loader
template <int ROWS, int KC, typename T>
DI void load_one(char* s, const T* G, size_t ldg) {
    constexpr int SA = KC + 8;
#pragma unroll 4
    for (int i = threadIdx.x; i < ROWS * KC / 8; i += 256) {
        int r = i / (KC / 8), c = (i % (KC / 8)) * 8;
        *(uint4*)(s + (r * SA + c) * 2) = *(const uint4*)(G + (size_t)r * ldg + c);
    }
}
// fp32 -> single fp16 converting loader
template <int ROWS, int KC>
DI void load_cvt_h(char* s, const float* G, size_t ldg) {
    constexpr int SA = KC + 8;
#pragma unroll 4
    for (int i = threadIdx.x; i < ROWS * KC / 4; i += 256) {
        int r = i / (KC / 4), c = (i % (KC / 4)) * 4;
        float4 v = *(const float4*)(G + (size_t)r * ldg + c);
        HF4 Hh;
        Hh.b[0] = __float2half_rn(v.x); Hh.b[1] = __float2half_rn(v.y);
        Hh.b[2] = __float2half_rn(v.z); Hh.b[3] = __float2half_rn(v.w);
        *(uint2*)(s + (r * SA + c) * 2) = Hh.u;
    }
}

// fp16 chunk: A single, B single -> 1 product
template <int WN, int MT, int NT, int SA, int SB, int KSTEPS, bool BT>
DI void mma_chunk_h1(uint32_t aF, uint32_t bF, float (&acc)[MT][NT][4]) {
    int lane = threadIdx.x & 31, wid = threadIdx.x >> 5;
    int wm = wid / WN, wn = wid % WN;
#pragma unroll
    for (int kk = 0; kk < KSTEPS; kk++) {
        uint32_t af[MT][4], bf[NT][2];
#pragma unroll
        for (int mt = 0; mt < MT; mt++) {
            uint32_t off = (uint32_t)(((wm * MT * 16 + mt * 16 + (lane & 15)) * SA
                                       + kk * 16 + (lane >> 4) * 8) * 2);
            ldsm4(af[mt], aF + off);
        }
#pragma unroll
        for (int nt = 0; nt < NT; nt += 2) {
            uint32_t off;
            if (BT)
                off = (uint32_t)(((kk * 16 + (lane & 15)) * SB
                                  + wn * NT * 8 + nt * 8 + (lane >> 4) * 8) * 2);
            else
                off = (uint32_t)(((wn * NT * 8 + nt * 8 + ((lane >> 4) << 3) + (lane & 7)) * SB
                                  + kk * 16 + (((lane >> 3) & 1) << 3)) * 2);
            uint32_t r[4];
            if (BT) ldsm4t(r, bF + off); else ldsm4(r, bF + off);
            bf[nt][0] = r[0]; bf[nt][1] = r[1]; bf[nt + 1][0] = r[2]; bf[nt + 1][1] = r[3];
        }
#pragma unroll
        for (int mt = 0; mt < MT; mt++)
#pragma unroll
            for (int nt = 0; nt < NT; nt++)
                mma16816h(acc[mt][nt], af[mt], bf[nt]);
    }
}

// ---------------- conversion kernels ----------------
__global__ __launch_bounds__(256) void c0_wt(const float* Wq, const float* Wk,
                                             const float* Wv, const float* Wp) {
    __shared__ float smt[32][33];
    int mat = blockIdx.z;
    const float* W = mat == 0 ? Wq : mat == 1 ? Wk : mat == 2 ? Wv : Wp;
    int nblk = blockIdx.x * 32, kblk = blockIdx.y * 32;
    for (int i = threadIdx.x; i < 1024; i += 256) {
        int r = i >> 5, c = i & 31;
        smt[r][c] = W[(size_t)(kblk + r) * 1024 + nblk + c];
    }
    __syncthreads();
    for (int i = threadIdx.x; i < 1024; i += 256) {
        int n = i >> 5, k = i & 31;
        size_t o = (size_t)mat * 1048576 + (size_t)(nblk + n) * 1024 + kblk + k;
        g_wtf[o] = __float2half_rn(smt[k][n]);
    }
}
__global__ __launch_bounds__(256) void c1_x(const float* q, const float* k, const float* v) {
    int z = blockIdx.y;
    const float* X = z == 0 ? q : z == 1 ? k : v;
    size_t idx = ((size_t)blockIdx.x * 256 + threadIdx.x) * 4;
    float4 t = *(const float4*)&X[idx];
    HF4 Hh;
    Hh.b[0] = __float2half_rn(t.x); Hh.b[1] = __float2half_rn(t.y);
    Hh.b[2] = __float2half_rn(t.z); Hh.b[3] = __float2half_rn(t.w);
    *(uint2*)&g_xf[(size_t)z * 4194304 + idx] = Hh.u;
}
__global__ __launch_bounds__(256) void c2_vt() {
    __shared__ __half smh[64][65];
    int sblk = blockIdx.x * 64, bh = blockIdx.y;
    size_t ibase = (size_t)bh * 65536;
    for (int i = threadIdx.x; i < 4096; i += 256) {
        int s = i >> 6, d = i & 63;
        smh[s][d] = g_vf[ibase + (size_t)(sblk + s) * 64 + d];
    }
    __syncthreads();
    for (int i = threadIdx.x; i < 4096; i += 256) {
        int d = i >> 6, s = i & 63;
        g_vtf[ibase + (size_t)d * 1024 + sblk + s] = smh[s][d];
    }
}

// ---------------- G1: q/k/v = X @ W^T + b (1 product, cp.async) ----------------
__global__ __launch_bounds__(256) void g1_qkv(const float* bq, const float* bk, const float* bv) {
    extern __shared__ char sm[];
    uint32_t smb = smem_u32(sm);
    constexpr int TS = 128 * 72 * 2;       // 18432 per tile
    constexpr int STG = 2 * TS;            // A + B
    int z = blockIdx.z, m0 = blockIdx.y * 128, n0 = blockIdx.x * 128;
    const __half* Af = g_xf + (size_t)z * 4194304 + (size_t)m0 * 1024;
    const __half* Bf = g_wtf + (size_t)z * 1048576 + (size_t)n0 * 1024;
    float acc[4][4][4] = {};
    auto issue = [&](int c) {
        uint32_t b = smb + (uint32_t)(c & 1) * STG;
        cp_one<128, 64>(b, Af + c * 64, 1024);
        cp_one<128, 64>(b + TS, Bf + c * 64, 1024);
        cp_commit();
    };
    issue(0);
    for (int c = 0; c < 16; c++) {
        if (c < 15) { issue(c + 1); cp_wait<1>(); } else cp_wait<0>();
        __syncthreads();
        uint32_t b = smb + (uint32_t)(c & 1) * STG;
        mma_chunk_h1<4, 4, 4, 72, 72, 4, false>(b, b + TS, acc);
        __syncthreads();
    }
    const float* bias = z == 0 ? bq : z == 1 ? bk : bv;
    float sc = z == 0 ? 0.125f : 1.f;
    __half* dst = z == 0 ? g_qf : z == 1 ? g_kf : g_vf;
    int lane = threadIdx.x & 31, wid = threadIdx.x >> 5, wm = wid / 4, wn = wid % 4;
#pragma unroll
    for (int mt = 0; mt < 4; mt++)
#pragma unroll
        for (int nt = 0; nt < 4; nt++)
#pragma unroll
            for (int hf = 0; hf < 2; hf++) {
                int m = m0 + wm * 64 + mt * 16 + (lane >> 2) + hf * 8;
                int n = n0 + wn * 32 + nt * 8 + (lane & 3) * 2;
                float v0 = (acc[mt][nt][hf * 2] + bias[n]) * sc;
                float v1 = (acc[mt][nt][hf * 2 + 1] + bias[n + 1]) * sc;
                int b = m >> 10, s = m & 1023, h = n >> 6, d = n & 63;
                size_t o = ((size_t)((b << 4) + h) * 1024 + s) * 64 + d;
                HF2 P;
                P.b[0] = __float2half_rn(v0); P.b[1] = __float2half_rn(v1);
                *(uint32_t*)&dst[o] = P.u;
            }
}

// ---------------- K3: g_we[s][bh][t] = fp16 edge-key logits ----------------
__global__ __launch_bounds__(256) void k3_edge(const float* __restrict__ ek) {
    extern __shared__ char sm[];
    char *aF = sm, *bF = sm + 9216;
    uint32_t aFu = smem_u32(aF), bFu = smem_u32(bF);
    int s = blockIdx.y, t0 = blockIdx.x * 128;
    float acc[2][4][4] = {};
    load_one<64, 64>(aF, g_qf + (size_t)s * 64, 65536);
    load_cvt_h<128, 64>(bF, ek + (size_t)s * 65536 + (size_t)t0 * 64, 64);
    __syncthreads();
    mma_chunk_h1<4, 2, 4, 72, 72, 4, false>(aFu, bFu, acc);
    int lane = threadIdx.x & 31, wid = threadIdx.x >> 5, wm = wid / 4, wn = wid % 4;
    size_t sbase = (size_t)s * 65536;
#pragma unroll
    for (int mt = 0; mt < 2; mt++)
#pragma unroll
        for (int nt = 0; nt < 4; nt++)
#pragma unroll
            for (int hf = 0; hf < 2; hf++) {
                int bh = wm * 32 + mt * 16 + (lane >> 2) + hf * 8;
                int t = t0 + wn * 32 + nt * 8 + (lane & 3) * 2;
                HF2 P;
                P.b[0] = __float2half_rn(acc[mt][nt][hf * 2]);
                P.b[1] = __float2half_rn(acc[mt][nt][hf * 2 + 1]);
                *(uint32_t*)&g_we[sbase + (size_t)bh * 1024 + t] = P.u;
            }
}

// ---------------- G2S: content + bias + edge + softmax -> fp16 w [s][bh][t] ----------------
__global__ __launch_bounds__(256) void g2s(const float* __restrict__ attn_bias) {
    extern __shared__ char sm[];
    __shared__ float red[8][32];
    __shared__ float redc[32];
    constexpr int KTS = 128 * 72 * 2;       // 18432 per k stage
    uint32_t smb = smem_u32(sm);
    uint32_t qFu = smb;
    int s0 = blockIdx.x * 32, bh = blockIdx.y;
    int tid = threadIdx.x, lane = tid & 31, wn = tid >> 5;

    auto issueK = [&](int it) {
        uint32_t b = smb + 4608 + (uint32_t)(it & 1) * KTS;
        cp_one<128, 64>(b, g_kf + (size_t)bh * 65536 + (size_t)it * 8192, 64);
        cp_commit();
    };
    issueK(0);
    load_one<32, 64>(sm, g_qf + (size_t)bh * 65536 + (size_t)s0 * 64, 64);

    float acc[2][16][4] = {};
    for (int it = 0; it < 8; it++) {
        if (it < 7) { issueK(it + 1); cp_wait<1>(); } else cp_wait<0>();
        __syncthreads();
        uint32_t kFu = smb + 4608 + (uint32_t)(it & 1) * KTS;
#pragma unroll
        for (int kk = 0; kk < 4; kk++) {
            uint32_t ah[2][4], bf2[2][2];
#pragma unroll
            for (int mt = 0; mt < 2; mt++) {
                uint32_t off = (uint32_t)(((mt * 16 + (lane & 15)) * 72
                                           + kk * 16 + (lane >> 4) * 8) * 2);
                ldsm4(ah[mt], qFu + off);
            }
            {
                uint32_t off = (uint32_t)(((wn * 16 + ((lane >> 4) << 3) + (lane & 7)) * 72
                                           + kk * 16 + (((lane >> 3) & 1) << 3)) * 2);
                uint32_t r[4];
                ldsm4(r, kFu + off);
                bf2[0][0] = r[0]; bf2[0][1] = r[1]; bf2[1][0] = r[2]; bf2[1][1] = r[3];
            }
#pragma unroll
            for (int mt = 0; mt < 2; mt++)
#pragma unroll
                for (int ntl = 0; ntl < 2; ntl++)
                    mma16816h(acc[mt][it * 2 + ntl], ah[mt], bf2[ntl]);
        }
        __syncthreads();
    }

    // stage g_we slab (coalesced) into smem, then add bias (fp32) + edge
    __half* stg = (__half*)sm;   // 32 x 1040
    for (int i = tid; i < 32 * 128; i += 256) {
        int rr = i >> 7, cc = (i & 127) * 8;
        *(uint4*)&stg[rr * 1040 + cc] =
            *(const uint4*)&g_we[(size_t)(s0 + rr) * 65536 + (size_t)bh * 1024 + cc];
    }
    __syncthreads();

    size_t bbase = (size_t)bh * 1048576;
#pragma unroll
    for (int mt = 0; mt < 2; mt++)
#pragma unroll
        for (int ntg = 0; ntg < 16; ntg++) {
            int sl = mt * 16 + (lane >> 2);
            int t = (ntg >> 1) * 128 + wn * 16 + (ntg & 1) * 8 + (lane & 3) * 2;
            float2 b0 = *(const float2*)&attn_bias[bbase + (size_t)(s0 + sl) * 1024 + t];
            float2 b1 = *(const float2*)&attn_bias[bbase + (size_t)(s0 + sl + 8) * 1024 + t];
            HF2 e0, e1;
            e0.u = *(const uint32_t*)&stg[sl * 1040 + t];
            e1.u = *(const uint32_t*)&stg[(sl + 8) * 1040 + t];
            acc[mt][ntg][0] += b0.x + __half2float(e0.b[0]);
            acc[mt][ntg][1] += b0.y + __half2float(e0.b[1]);
            acc[mt][ntg][2] += b1.x + __half2float(e1.b[0]);
            acc[mt][ntg][3] += b1.y + __half2float(e1.b[1]);
        }

    float rv[4];
#pragma unroll
    for (int r = 0; r < 4; r++) rv[r] = -1e30f;
#pragma unroll
    for (int mt = 0; mt < 2; mt++)
#pragma unroll
        for (int ntg = 0; ntg < 16; ntg++)
#pragma unroll
            for (int e = 0; e < 4; e++) {
                int r = mt * 2 + (e >> 1);
                rv[r] = fmaxf(rv[r], acc[mt][ntg][e]);
            }
#pragma unroll
    for (int r = 0; r < 4; r++) {
        rv[r] = fmaxf(rv[r], __shfl_xor_sync(~0u, rv[r], 1));
        rv[r] = fmaxf(rv[r], __shfl_xor_sync(~0u, rv[r], 2));
    }
    if ((lane & 3) == 0)
#pragma unroll
        for (int r = 0; r < 4; r++)
            red[wn][(r >> 1) * 16 + (lane >> 2) + (r & 1) * 8] = rv[r];
    __syncthreads();
    if (tid < 32) {
        float m = red[0][tid];
#pragma unroll
        for (int w = 1; w < 8; w++) m = fmaxf(m, red[w][tid]);
        redc[tid] = m;
    }
    __syncthreads();
    float rmax[4];
#pragma unroll
    for (int r = 0; r < 4; r++) rmax[r] = redc[(r >> 1) * 16 + (lane >> 2) + (r & 1) * 8];
    __syncthreads();

#pragma unroll
    for (int r = 0; r < 4; r++) rv[r] = 0.f;
#pragma unroll
    for (int mt = 0; mt < 2; mt++)
#pragma unroll
        for (int ntg = 0; ntg < 16; ntg++)
#pragma unroll
            for (int e = 0; e < 4; e++) {
                int r = mt * 2 + (e >> 1);
                float v = __expf(acc[mt][ntg][e] - rmax[r]);
                acc[mt][ntg][e] = v;
                rv[r] += v;
            }
#pragma unroll
    for (int r = 0; r < 4; r++) {
        rv[r] += __shfl_xor_sync(~0u, rv[r], 1);
        rv[r] += __shfl_xor_sync(~0u, rv[r], 2);
    }
    if ((lane & 3) == 0)
#pragma unroll
        for (int r = 0; r < 4; r++)
            red[wn][(r >> 1) * 16 + (lane >> 2) + (r & 1) * 8] = rv[r];
    __syncthreads();
    if (tid < 32) {
        float sval = red[0][tid];
#pragma unroll
        for (int w = 1; w < 8; w++) sval += red[w][tid];
        redc[tid] = 1.0f / sval;
    }
    __syncthreads();
    float rinv[4];
#pragma unroll
    for (int r = 0; r < 4; r++) rinv[r] = redc[(r >> 1) * 16 + (lane >> 2) + (r & 1) * 8];
    __syncthreads();

#pragma unroll
    for (int mt = 0; mt < 2; mt++)
#pragma unroll
        for (int ntg = 0; ntg < 16; ntg++) {
            int sl = mt * 16 + (lane >> 2);
            int t = (ntg >> 1) * 128 + wn * 16 + (ntg & 1) * 8 + (lane & 3) * 2;
            *(__half2*)&stg[sl * 1040 + t] =
                __floats2half2_rn(acc[mt][ntg][0] * rinv[mt * 2],
                                  acc[mt][ntg][1] * rinv[mt * 2]);
            *(__half2*)&stg[(sl + 8) * 1040 + t] =
                __floats2half2_rn(acc[mt][ntg][2] * rinv[mt * 2 + 1],
                                  acc[mt][ntg][3] * rinv[mt * 2 + 1]);
        }
    __syncthreads();
    for (int i = tid; i < 32 * 128; i += 256) {
        int rr = i >> 7, cc = (i & 127) * 8;
        *(uint4*)&g_wf[(size_t)(s0 + rr) * 65536 + (size_t)bh * 1024 + cc] =
            *(const uint4*)&stg[rr * 1040 + cc];
    }
}

// ---------------- G5: att = W @ V (1 product, cp.async) ----------------
__global__ __launch_bounds__(256) void g5_pv() {
    extern __shared__ char sm[];
    uint32_t smb = smem_u32(sm);
    constexpr int ATS = 128 * 72 * 2;       // 18432
    constexpr int BTS = 64 * 72 * 2;        // 9216
    constexpr int STG = ATS + BTS;          // 27648
    int bh = blockIdx.y, m0 = blockIdx.x * 128;
    const __half* A = g_wf + (size_t)m0 * 65536 + (size_t)bh * 1024;  // [s][bh][t]
    const __half* Bf = g_vtf + (size_t)bh * 65536;
    float acc[2][4][4] = {};
    auto issue = [&](int c) {
        uint32_t b = smb + (uint32_t)(c & 1) * STG;
        cp_one<128, 64>(b, A + c * 64, 65536);
        cp_one<64, 64>(b + ATS, Bf + c * 64, 1024);
        cp_commit();
    };
    issue(0);
    for (int c = 0; c < 16; c++) {
        if (c < 15) { issue(c + 1); cp_wait<1>(); } else cp_wait<0>();
        __syncthreads();
        uint32_t b = smb + (uint32_t)(c & 1) * STG;
        mma_chunk_h1<2, 2, 4, 72, 72, 4, false>(b, b + ATS, acc);
        __syncthreads();
    }
    int lane = threadIdx.x & 31, wid = threadIdx.x >> 5, wm = wid / 2, wn = wid % 2;
    int b = bh >> 4, h = bh & 15;
#pragma unroll
    for (int mt = 0; mt < 2; mt++)
#pragma unroll
        for (int nt = 0; nt < 4; nt++)
#pragma unroll
            for (int hf = 0; hf < 2; hf++) {
                int s = m0 + wm * 32 + mt * 16 + (lane >> 2) + hf * 8;
                int d = wn * 32 + nt * 8 + (lane & 3) * 2;
                size_t o = ((size_t)(b * 1024 + s)) * 1024 + h * 64 + d;
                float2 vv;
                vv.x = acc[mt][nt][hf * 2];
                vv.y = acc[mt][nt][hf * 2 + 1];
                *(float2*)&g_att[o] = vv;
            }
}

// ---------------- K6: attf = att + W @ EV_s (pipelined ev stream) ----------------
__global__ __launch_bounds__(256) void k6_ev(const float* __restrict__ ev) {
    extern __shared__ char sm[];
    char *aF = sm, *bFh = sm + 17408;
    uint32_t aFu = smem_u32(aF), bFu = smem_u32(bFh);
    uint32_t brawu = smem_u32(sm + 35840);
    int s = blockIdx.x;
    const float* evs = ev + (size_t)s * 65536;
    float acc[1][4][4] = {};
    auto issueB = [&](int c) {
        uint32_t dst = brawu + (uint32_t)(c & 1) * 32768;
        const float* src = evs + (size_t)c * 8192;   // contiguous 32KB chunk
#pragma unroll
        for (int i = threadIdx.x; i < 2048; i += 256)
            cp16(dst + (uint32_t)i * 16, src + i * 4);
        cp_commit();
    };
    issueB(0);
    for (int c = 0; c < 8; c++) {
        // A chunk: w[all 64 bh][t chunk] — contiguous [s][bh][t] layout
        load_one<64, 128>(aF, g_wf + (size_t)s * 65536 + c * 128, 1024);
        if (c < 7) { issueB(c + 1); cp_wait<1>(); } else cp_wait<0>();
        __syncthreads();
        // convert raw fp32 ev chunk -> padded fp16 tile [128 t][64 d] (SB=72)
        const float* bw = (const float*)(sm + 35840 + (c & 1) * 32768);
#pragma unroll
        for (int i = threadIdx.x; i < 2048; i += 256) {
            int r = i >> 4, cc = (i & 15) * 4;
            float4 v = *(const float4*)(bw + r * 64 + cc);
            HF4 Hh;
            Hh.b[0] = __float2half_rn(v.x); Hh.b[1] = __float2half_rn(v.y);
            Hh.b[2] = __float2half_rn(v.z); Hh.b[3] = __float2half_rn(v.w);
            *(uint2*)(bFh + (r * 72 + cc) * 2) = Hh.u;
        }
        __syncthreads();
        mma_chunk_h1<2, 1, 4, 136, 72, 8, true>(aFu, bFu, acc);
        __syncthreads();
    }
    int lane = threadIdx.x & 31, wid = threadIdx.x >> 5, wm = wid / 2, wn = wid % 2;
#pragma unroll
    for (int nt = 0; nt < 4; nt++)
#pragma unroll
        for (int hf = 0; hf < 2; hf++) {
            int bh = wm * 16 + (lane >> 2) + hf * 8;
            int d = wn * 32 + nt * 8 + (lane & 3) * 2;
            int b = bh >> 4, h = bh & 15;
            size_t o = ((size_t)(b * 1024 + s)) * 1024 + h * 64 + d;
            float2 cur = *(float2*)&g_att[o];
            HF2 P;
            P.b[0] = __float2half_rn(cur.x + acc[0][nt][hf * 2]);
            P.b[1] = __float2half_rn(cur.y + acc[0][nt][hf * 2 + 1]);
            *(uint32_t*)&g_attf[o] = P.u;
        }
}

// ---------------- G7: out = att @ Wp^T + bp (1 product, cp.async) ----------------
__global__ __launch_bounds__(256) void g7_out(const float* __restrict__ bp, float* __restrict__ out) {
    extern __shared__ char sm[];
    uint32_t smb = smem_u32(sm);
    constexpr int TS = 128 * 72 * 2;
    constexpr int STG = 2 * TS;
    int m0 = blockIdx.y * 128, n0 = blockIdx.x * 128;
    const __half* Bf = g_wtf + (size_t)3 * 1048576 + (size_t)n0 * 1024;
    float acc[4][4][4] = {};
    auto issue = [&](int c) {
        uint32_t b = smb + (uint32_t)(c & 1) * STG;
        cp_one<128, 64>(b, g_attf + (size_t)m0 * 1024 + c * 64, 1024);
        cp_one<128, 64>(b + TS, Bf + c * 64, 1024);
        cp_commit();
    };
    issue(0);
    for (int c = 0; c < 16; c++) {
        if (c < 15) { issue(c + 1); cp_wait<1>(); } else cp_wait<0>();
        __syncthreads();
        uint32_t b = smb + (uint32_t)(c & 1) * STG;
        mma_chunk_h1<4, 4, 4, 72, 72, 4, false>(b, b + TS, acc);
        __syncthreads();
    }
    int lane = threadIdx.x & 31, wid = threadIdx.x >> 5, wm = wid / 4, wn = wid % 4;
#pragma unroll
    for (int mt = 0; mt < 4; mt++)
#pragma unroll
        for (int nt = 0; nt < 4; nt++)
#pragma unroll
            for (int hf = 0; hf < 2; hf++) {
                int m = m0 + wm * 64 + mt * 16 + (lane >> 2) + hf * 8;
                int n = n0 + wn * 32 + nt * 8 + (lane & 3) * 2;
                float2 bb = *(const float2*)&bp[n];
                float2 vv;
                vv.x = acc[mt][nt][hf * 2] + bb.x;
                vv.y = acc[mt][nt][hf * 2 + 1] + bb.y;
                *(float2*)&out[(size_t)m * 1024 + n] = vv;
            }
}

// ---------------- launch ----------------
extern "C" void kernel_launch(void* const* d_in, const int* in_sizes, int n_in,
                              void* d_out, int out_size) {
    const float* queries     = (const float*)d_in[0];
    const float* keys        = (const float*)d_in[1];
    const float* values      = (const float*)d_in[2];
    const float* edges_key   = (const float*)d_in[3];
    const float* edges_value = (const float*)d_in[4];
    const float* attn_bias   = (const float*)d_in[5];
    const float* Wq = (const float*)d_in[6];  const float* bq = (const float*)d_in[7];
    const float* Wk = (const float*)d_in[8];  const float* bk = (const float*)d_in[9];
    const float* Wv = (const float*)d_in[10]; const float* bv = (const float*)d_in[11];
    const float* Wp = (const float*)d_in[12]; const float* bp = (const float*)d_in[13];

    cudaFuncSetAttribute(g1_qkv,  cudaFuncAttributeMaxDynamicSharedMemorySize, 73728);
    cudaFuncSetAttribute(k3_edge, cudaFuncAttributeMaxDynamicSharedMemorySize, 27648);
    cudaFuncSetAttribute(g2s,     cudaFuncAttributeMaxDynamicSharedMemorySize, 66560);
    cudaFuncSetAttribute(g5_pv,   cudaFuncAttributeMaxDynamicSharedMemorySize, 55296);
    cudaFuncSetAttribute(k6_ev,   cudaFuncAttributeMaxDynamicSharedMemorySize, 101376);
    cudaFuncSetAttribute(g7_out,  cudaFuncAttributeMaxDynamicSharedMemorySize, 73728);

    c0_wt<<<dim3(32, 32, 4), 256>>>(Wq, Wk, Wv, Wp);
    c1_x<<<dim3(4096, 3), 256>>>(queries, keys, values);
    g1_qkv<<<dim3(8, 32, 3), 256, 73728>>>(bq, bk, bv);
    c2_vt<<<dim3(16, 64), 256>>>();
    k3_edge<<<dim3(8, 1024), 256, 27648>>>(edges_key);
    g2s<<<dim3(32, 64), 256, 66560>>>(attn_bias);
    g5_pv<<<dim3(8, 64), 256, 55296>>>();
    k6_ev<<<1024, 256, 101376>>>(edges_value);
    g7_out<<<dim3(8, 32), 256, 73728>>>(bp, (float*)d_out);
}

// round 15
// speedup vs baseline: 1.0550x; 1.0479x over previous
#include <cuda_runtime.h>
#include <cuda_bf16.h>
#include <cuda_fp16.h>
#include <cstdint>

// B=4, S=1024, E=1024, H=16, D=64, BH=64.
// R11 base (PV fused into g2s; g5/c2_vt removed) + fp16 att_pv intermediate
// + k3 2-chunk q-reuse. All GEMMs single-fp16 mma.sync, cp.async pipelines.

#define DI __device__ __forceinline__

// ---------------- device scratch ----------------
__device__ __align__(128) __half g_we[67108864];                // fp16 edge logits [s][bh][t]
__device__ __align__(128) __half g_wf[67108864];                // fp16 softmax weights [s][bh][t]
__device__ __align__(128) __half g_attpv[4194304];              // fp16 PV partial att [b*s][h*d]
__device__ __align__(128) __half g_xf[3*4194304];               // X fp16 [z][m][k]
__device__ __align__(128) __half g_wtf[4*1048576];              // W^T fp16 [mat][n][k]
__device__ __align__(128) __half g_qf[4194304];                 // [bh][s][d] scaled q
__device__ __align__(128) __half g_kf[4194304];                 // [bh][t][d]
__device__ __align__(128) __half g_vf[4194304];                 // [bh][s][d]
__device__ __align__(128) __half g_attf[4194304];               // final att fp16 [b*s][h*d]

// ---------------- helpers ----------------
union HF2 { __half b[2]; uint32_t u; };
union HF4 { __half b[4]; uint2 u; };

DI uint32_t smem_u32(const void* p) {
    uint32_t a;
    asm("{ .reg .u64 t; cvta.to.shared.u64 t, %1; cvt.u32.u64 %0, t; }" : "=r"(a) : "l"(p));
    return a;
}
DI void ldsm4(uint32_t* r, uint32_t a) {
    asm volatile("ldmatrix.sync.aligned.m8n8.x4.shared.b16 {%0,%1,%2,%3}, [%4];"
        : "=r"(r[0]), "=r"(r[1]), "=r"(r[2]), "=r"(r[3]) : "r"(a));
}
DI void ldsm4t(uint32_t* r, uint32_t a) {
    asm volatile("ldmatrix.sync.aligned.m8n8.x4.trans.shared.b16 {%0,%1,%2,%3}, [%4];"
        : "=r"(r[0]), "=r"(r[1]), "=r"(r[2]), "=r"(r[3]) : "r"(a));
}
DI void mma16816h(float* d, const uint32_t* a, const uint32_t* b) {
    asm volatile("mma.sync.aligned.m16n8k16.row.col.f32.f16.f16.f32 "
        "{%0,%1,%2,%3}, {%4,%5,%6,%7}, {%8,%9}, {%0,%1,%2,%3};"
        : "+f"(d[0]), "+f"(d[1]), "+f"(d[2]), "+f"(d[3])
        : "r"(a[0]), "r"(a[1]), "r"(a[2]), "r"(a[3]), "r"(b[0]), "r"(b[1]));
}
DI void cp16(uint32_t d, const void* s) {
    asm volatile("cp.async.cg.shared.global [%0], [%1], 16;" :: "r"(d), "l"(s));
}
DI void cp_commit() { asm volatile("cp.async.commit_group;" ::: "memory"); }
template <int N> DI void cp_wait() {
    asm volatile("cp.async.wait_group %0;" :: "n"(N) : "memory");
}

template <int ROWS, int KC, typename T>
DI void cp_one(uint32_t s, const T* G, size_t ldg) {
    constexpr int SA = KC + 8;
#pragma unroll
    for (int i = threadIdx.x; i < ROWS * KC / 8; i += 256) {
        int r = i / (KC / 8), c = (i % (KC / 8)) * 8;
        cp16(s + (uint32_t)(r * SA + c) * 2, G + (size_t)r * ldg + c);
    }
}
template <int ROWS, int KC, typename T>
DI void load_one(char* s, const T* G, size_t ldg) {
    constexpr int SA = KC + 8;
#pragma unroll 4
    for (int i = threadIdx.x; i < ROWS * KC / 8; i += 256) {
        int r = i / (KC / 8), c = (i % (KC / 8)) * 8;
        *(uint4*)(s + (r * SA + c) * 2) = *(const uint4*)(G + (size_t)r * ldg + c);
    }
}
template <int ROWS, int KC>
DI void load_cvt_h(char* s, const float* G, size_t ldg) {
    constexpr int SA = KC + 8;
#pragma unroll 4
    for (int i = threadIdx.x; i < ROWS * KC / 4; i += 256) {
        int r = i / (KC / 4), c = (i % (KC / 4)) * 4;
        float4 v = *(const float4*)(G + (size_t)r * ldg + c);
        HF4 Hh;
        Hh.b[0] = __float2half_rn(v.x); Hh.b[1] = __float2half_rn(v.y);
        Hh.b[2] = __float2half_rn(v.z); Hh.b[3] = __float2half_rn(v.w);
        *(uint2*)(s + (r * SA + c) * 2) = Hh.u;
    }
}

// fp16 chunk: A single, B single -> 1 product
template <int WN, int MT, int NT, int SA, int SB, int KSTEPS, bool BT>
DI void mma_chunk_h1(uint32_t aF, uint32_t bF, float (&acc)[MT][NT][4]) {
    int lane = threadIdx.x & 31, wid = threadIdx.x >> 5;
    int wm = wid / WN, wn = wid % WN;
#pragma unroll
    for (int kk = 0; kk < KSTEPS; kk++) {
        uint32_t af[MT][4], bf[NT][2];
#pragma unroll
        for (int mt = 0; mt < MT; mt++) {
            uint32_t off = (uint32_t)(((wm * MT * 16 + mt * 16 + (lane & 15)) * SA
                                       + kk * 16 + (lane >> 4) * 8) * 2);
            ldsm4(af[mt], aF + off);
        }
#pragma unroll
        for (int nt = 0; nt < NT; nt += 2) {
            uint32_t off;
            if (BT)
                off = (uint32_t)(((kk * 16 + (lane & 15)) * SB
                                  + wn * NT * 8 + nt * 8 + (lane >> 4) * 8) * 2);
            else
                off = (uint32_t)(((wn * NT * 8 + nt * 8 + ((lane >> 4) << 3) + (lane & 7)) * SB
                                  + kk * 16 + (((lane >> 3) & 1) << 3)) * 2);
            uint32_t r[4];
            if (BT) ldsm4t(r, bF + off); else ldsm4(r, bF + off);
            bf[nt][0] = r[0]; bf[nt][1] = r[1]; bf[nt + 1][0] = r[2]; bf[nt + 1][1] = r[3];
        }
#pragma unroll
        for (int mt = 0; mt < MT; mt++)
#pragma unroll
            for (int nt = 0; nt < NT; nt++)
                mma16816h(acc[mt][nt], af[mt], bf[nt]);
    }
}

// ---------------- conversion kernels ----------------
__global__ __launch_bounds__(256) void c0_wt(const float* Wq, const float* Wk,
                                             const float* Wv, const float* Wp) {
    __shared__ float smt[32][33];
    int mat = blockIdx.z;
    const float* W = mat == 0 ? Wq : mat == 1 ? Wk : mat == 2 ? Wv : Wp;
    int nblk = blockIdx.x * 32, kblk = blockIdx.y * 32;
    for (int i = threadIdx.x; i < 1024; i += 256) {
        int r = i >> 5, c = i & 31;
        smt[r][c] = W[(size_t)(kblk + r) * 1024 + nblk + c];
    }
    __syncthreads();
    for (int i = threadIdx.x; i < 1024; i += 256) {
        int n = i >> 5, k = i & 31;
        size_t o = (size_t)mat * 1048576 + (size_t)(nblk + n) * 1024 + kblk + k;
        g_wtf[o] = __float2half_rn(smt[k][n]);
    }
}
__global__ __launch_bounds__(256) void c1_x(const float* q, const float* k, const float* v) {
    int z = blockIdx.y;
    const float* X = z == 0 ? q : z == 1 ? k : v;
    size_t idx = ((size_t)blockIdx.x * 256 + threadIdx.x) * 4;
    float4 t = *(const float4*)&X[idx];
    HF4 Hh;
    Hh.b[0] = __float2half_rn(t.x); Hh.b[1] = __float2half_rn(t.y);
    Hh.b[2] = __float2half_rn(t.z); Hh.b[3] = __float2half_rn(t.w);
    *(uint2*)&g_xf[(size_t)z * 4194304 + idx] = Hh.u;
}

// ---------------- G1: q/k/v = X @ W^T + b (1 product, cp.async) ----------------
__global__ __launch_bounds__(256) void g1_qkv(const float* bq, const float* bk, const float* bv) {
    extern __shared__ char sm[];
    uint32_t smb = smem_u32(sm);
    constexpr int TS = 128 * 72 * 2;
    constexpr int STG = 2 * TS;
    int z = blockIdx.z, m0 = blockIdx.y * 128, n0 = blockIdx.x * 128;
    const __half* Af = g_xf + (size_t)z * 4194304 + (size_t)m0 * 1024;
    const __half* Bf = g_wtf + (size_t)z * 1048576 + (size_t)n0 * 1024;
    float acc[4][4][4] = {};
    auto issue = [&](int c) {
        uint32_t b = smb + (uint32_t)(c & 1) * STG;
        cp_one<128, 64>(b, Af + c * 64, 1024);
        cp_one<128, 64>(b + TS, Bf + c * 64, 1024);
        cp_commit();
    };
    issue(0);
    for (int c = 0; c < 16; c++) {
        if (c < 15) { issue(c + 1); cp_wait<1>(); } else cp_wait<0>();
        __syncthreads();
        uint32_t b = smb + (uint32_t)(c & 1) * STG;
        mma_chunk_h1<4, 4, 4, 72, 72, 4, false>(b, b + TS, acc);
        __syncthreads();
    }
    const float* bias = z == 0 ? bq : z == 1 ? bk : bv;
    float sc = z == 0 ? 0.125f : 1.f;
    __half* dst = z == 0 ? g_qf : z == 1 ? g_kf : g_vf;
    int lane = threadIdx.x & 31, wid = threadIdx.x >> 5, wm = wid / 4, wn = wid % 4;
#pragma unroll
    for (int mt = 0; mt < 4; mt++)
#pragma unroll
        for (int nt = 0; nt < 4; nt++)
#pragma unroll
            for (int hf = 0; hf < 2; hf++) {
                int m = m0 + wm * 64 + mt * 16 + (lane >> 2) + hf * 8;
                int n = n0 + wn * 32 + nt * 8 + (lane & 3) * 2;
                float v0 = (acc[mt][nt][hf * 2] + bias[n]) * sc;
                float v1 = (acc[mt][nt][hf * 2 + 1] + bias[n + 1]) * sc;
                int b = m >> 10, s = m & 1023, h = n >> 6, d = n & 63;
                size_t o = ((size_t)((b << 4) + h) * 1024 + s) * 64 + d;
                HF2 P;
                P.b[0] = __float2half_rn(v0); P.b[1] = __float2half_rn(v1);
                *(uint32_t*)&dst[o] = P.u;
            }
}

// ---------------- K3: g_we[s][bh][t] = fp16 edge-key logits (2 chunks/block) ----------------
__global__ __launch_bounds__(256) void k3_edge(const float* __restrict__ ek) {
    extern __shared__ char sm[];
    char *aF = sm, *bF = sm + 9216;
    uint32_t aFu = smem_u32(aF), bFu = smem_u32(bF);
    int s = blockIdx.y, t00 = blockIdx.x * 256;
    int lane = threadIdx.x & 31, wid = threadIdx.x >> 5, wm = wid / 4, wn = wid % 4;
    size_t sbase = (size_t)s * 65536;
    load_one<64, 64>(aF, g_qf + (size_t)s * 64, 65536);
#pragma unroll
    for (int ch = 0; ch < 2; ch++) {
        int t0 = t00 + ch * 128;
        load_cvt_h<128, 64>(bF, ek + (size_t)s * 65536 + (size_t)t0 * 64, 64);
        __syncthreads();
        float acc[2][4][4] = {};
        mma_chunk_h1<4, 2, 4, 72, 72, 4, false>(aFu, bFu, acc);
#pragma unroll
        for (int mt = 0; mt < 2; mt++)
#pragma unroll
            for (int nt = 0; nt < 4; nt++)
#pragma unroll
                for (int hf = 0; hf < 2; hf++) {
                    int bh = wm * 32 + mt * 16 + (lane >> 2) + hf * 8;
                    int t = t0 + wn * 32 + nt * 8 + (lane & 3) * 2;
                    HF2 P;
                    P.b[0] = __float2half_rn(acc[mt][nt][hf * 2]);
                    P.b[1] = __float2half_rn(acc[mt][nt][hf * 2 + 1]);
                    *(uint32_t*)&g_we[sbase + (size_t)bh * 1024 + t] = P.u;
                }
        __syncthreads();
    }
}

// ---------- G2S: content+bias+edge logits, softmax, fp16 w, FUSED PV ----------
__global__ __launch_bounds__(256) void g2s(const float* __restrict__ attn_bias) {
    extern __shared__ char sm[];
    __shared__ float red[8][32];
    __shared__ float redc[32];
    constexpr int KTS = 128 * 72 * 2;
    uint32_t smb = smem_u32(sm);
    uint32_t qFu = smb;
    int s0 = blockIdx.x * 32, bh = blockIdx.y;
    int tid = threadIdx.x, lane = tid & 31, wn = tid >> 5;

    auto issueK = [&](int it) {
        uint32_t b = smb + 4608 + (uint32_t)(it & 1) * KTS;
        cp_one<128, 64>(b, g_kf + (size_t)bh * 65536 + (size_t)it * 8192, 64);
        cp_commit();
    };
    issueK(0);
    load_one<32, 64>(sm, g_qf + (size_t)bh * 65536 + (size_t)s0 * 64, 64);

    float acc[2][16][4] = {};
    for (int it = 0; it < 8; it++) {
        if (it < 7) { issueK(it + 1); cp_wait<1>(); } else cp_wait<0>();
        __syncthreads();
        uint32_t kFu = smb + 4608 + (uint32_t)(it & 1) * KTS;
#pragma unroll
        for (int kk = 0; kk < 4; kk++) {
            uint32_t ah[2][4], bf2[2][2];
#pragma unroll
            for (int mt = 0; mt < 2; mt++) {
                uint32_t off = (uint32_t)(((mt * 16 + (lane & 15)) * 72
                                           + kk * 16 + (lane >> 4) * 8) * 2);
                ldsm4(ah[mt], qFu + off);
            }
            {
                uint32_t off = (uint32_t)(((wn * 16 + ((lane >> 4) << 3) + (lane & 7)) * 72
                                           + kk * 16 + (((lane >> 3) & 1) << 3)) * 2);
                uint32_t r[4];
                ldsm4(r, kFu + off);
                bf2[0][0] = r[0]; bf2[0][1] = r[1]; bf2[1][0] = r[2]; bf2[1][1] = r[3];
            }
#pragma unroll
            for (int mt = 0; mt < 2; mt++)
#pragma unroll
                for (int ntl = 0; ntl < 2; ntl++)
                    mma16816h(acc[mt][it * 2 + ntl], ah[mt], bf2[ntl]);
        }
        __syncthreads();
    }

    // add attn_bias (fp32, [bh][s][t]) + edge logits (fp16, [s][bh][t])
    size_t bbase = (size_t)bh * 1048576;
#pragma unroll
    for (int mt = 0; mt < 2; mt++)
#pragma unroll
        for (int ntg = 0; ntg < 16; ntg++) {
            int sl = mt * 16 + (lane >> 2);
            int t = (ntg >> 1) * 128 + wn * 16 + (ntg & 1) * 8 + (lane & 3) * 2;
            float2 b0 = *(const float2*)&attn_bias[bbase + (size_t)(s0 + sl) * 1024 + t];
            float2 b1 = *(const float2*)&attn_bias[bbase + (size_t)(s0 + sl + 8) * 1024 + t];
            HF2 e0, e1;
            e0.u = *(const uint32_t*)&g_we[(size_t)(s0 + sl) * 65536 + (size_t)bh * 1024 + t];
            e1.u = *(const uint32_t*)&g_we[(size_t)(s0 + sl + 8) * 65536 + (size_t)bh * 1024 + t];
            acc[mt][ntg][0] += b0.x + __half2float(e0.b[0]);
            acc[mt][ntg][1] += b0.y + __half2float(e0.b[1]);
            acc[mt][ntg][2] += b1.x + __half2float(e1.b[0]);
            acc[mt][ntg][3] += b1.y + __half2float(e1.b[1]);
        }

    float rv[4];
#pragma unroll
    for (int r = 0; r < 4; r++) rv[r] = -1e30f;
#pragma unroll
    for (int mt = 0; mt < 2; mt++)
#pragma unroll
        for (int ntg = 0; ntg < 16; ntg++)
#pragma unroll
            for (int e = 0; e < 4; e++) {
                int r = mt * 2 + (e >> 1);
                rv[r] = fmaxf(rv[r], acc[mt][ntg][e]);
            }
#pragma unroll
    for (int r = 0; r < 4; r++) {
        rv[r] = fmaxf(rv[r], __shfl_xor_sync(~0u, rv[r], 1));
        rv[r] = fmaxf(rv[r], __shfl_xor_sync(~0u, rv[r], 2));
    }
    if ((lane & 3) == 0)
#pragma unroll
        for (int r = 0; r < 4; r++)
            red[wn][(r >> 1) * 16 + (lane >> 2) + (r & 1) * 8] = rv[r];
    __syncthreads();
    if (tid < 32) {
        float m = red[0][tid];
#pragma unroll
        for (int w = 1; w < 8; w++) m = fmaxf(m, red[w][tid]);
        redc[tid] = m;
    }
    __syncthreads();
    float rmax[4];
#pragma unroll
    for (int r = 0; r < 4; r++) rmax[r] = redc[(r >> 1) * 16 + (lane >> 2) + (r & 1) * 8];
    __syncthreads();

#pragma unroll
    for (int r = 0; r < 4; r++) rv[r] = 0.f;
#pragma unroll
    for (int mt = 0; mt < 2; mt++)
#pragma unroll
        for (int ntg = 0; ntg < 16; ntg++)
#pragma unroll
            for (int e = 0; e < 4; e++) {
                int r = mt * 2 + (e >> 1);
                float v = __expf(acc[mt][ntg][e] - rmax[r]);
                acc[mt][ntg][e] = v;
                rv[r] += v;
            }
#pragma unroll
    for (int r = 0; r < 4; r++) {
        rv[r] += __shfl_xor_sync(~0u, rv[r], 1);
        rv[r] += __shfl_xor_sync(~0u, rv[r], 2);
    }
    if ((lane & 3) == 0)
#pragma unroll
        for (int r = 0; r < 4; r++)
            red[wn][(r >> 1) * 16 + (lane >> 2) + (r & 1) * 8] = rv[r];
    __syncthreads();
    if (tid < 32) {
        float sval = red[0][tid];
#pragma unroll
        for (int w = 1; w < 8; w++) sval += red[w][tid];
        redc[tid] = 1.0f / sval;
    }
    __syncthreads();
    float rinv[4];
#pragma unroll
    for (int r = 0; r < 4; r++) rinv[r] = redc[(r >> 1) * 16 + (lane >> 2) + (r & 1) * 8];
    __syncthreads();

    // normalized fp16 w fragments (also A-fragments for PV)
    uint32_t wh[2][16][2];
#pragma unroll
    for (int mt = 0; mt < 2; mt++)
#pragma unroll
        for (int ntg = 0; ntg < 16; ntg++) {
            HF2 p0, p1;
            *(__half2*)&p0 = __floats2half2_rn(acc[mt][ntg][0] * rinv[mt * 2],
                                               acc[mt][ntg][1] * rinv[mt * 2]);
            *(__half2*)&p1 = __floats2half2_rn(acc[mt][ntg][2] * rinv[mt * 2 + 1],
                                               acc[mt][ntg][3] * rinv[mt * 2 + 1]);
            wh[mt][ntg][0] = p0.u;
            wh[mt][ntg][1] = p1.u;
        }

    // stage w to smem, coalesced g_wf write (k6 consumes it)
    __half* stg = (__half*)sm;   // 32 x 1040
#pragma unroll
    for (int mt = 0; mt < 2; mt++)
#pragma unroll
        for (int ntg = 0; ntg < 16; ntg++) {
            int sl = mt * 16 + (lane >> 2);
            int t = (ntg >> 1) * 128 + wn * 16 + (ntg & 1) * 8 + (lane & 3) * 2;
            *(uint32_t*)&stg[sl * 1040 + t] = wh[mt][ntg][0];
            *(uint32_t*)&stg[(sl + 8) * 1040 + t] = wh[mt][ntg][1];
        }
    __syncthreads();
    for (int i = tid; i < 32 * 128; i += 256) {
        int rr = i >> 7, cc = (i & 127) * 8;
        *(uint4*)&g_wf[(size_t)(s0 + rr) * 65536 + (size_t)bh * 1024 + cc] =
            *(const uint4*)&stg[rr * 1040 + cc];
    }
    __syncthreads();

    // ---- fused PV: att_pv[32 s][64 d] = w @ V, v streamed [t][d] via cp.async ----
    auto issueV = [&](int p) {
        uint32_t b = smb + (uint32_t)(p & 1) * 18432;
        cp_one<128, 64>(b, g_vf + (size_t)bh * 65536 + (size_t)p * 8192, 64);
        cp_commit();
    };
    issueV(0);
    float accpv[2][8][4] = {};
    for (int p = 0; p < 8; p++) {
        if (p < 7) { issueV(p + 1); cp_wait<1>(); } else cp_wait<0>();
        __syncthreads();
        uint32_t vb = smb + (uint32_t)(p & 1) * 18432;
        uint32_t bf[8][2];
#pragma unroll
        for (int nt = 0; nt < 8; nt += 2) {
            uint32_t off = (uint32_t)(((wn * 16 + (lane & 15)) * 72
                                       + nt * 8 + (lane >> 4) * 8) * 2);
            uint32_t r[4];
            ldsm4t(r, vb + off);
            bf[nt][0] = r[0]; bf[nt][1] = r[1]; bf[nt + 1][0] = r[2]; bf[nt + 1][1] = r[3];
        }
#pragma unroll
        for (int mt = 0; mt < 2; mt++) {
            uint32_t aR[4] = {wh[mt][2 * p][0], wh[mt][2 * p][1],
                              wh[mt][2 * p + 1][0], wh[mt][2 * p + 1][1]};
#pragma unroll
            for (int nd = 0; nd < 8; nd++)
                mma16816h(accpv[mt][nd], aR, bf[nd]);
        }
        __syncthreads();
    }

    // cross-warp reduction over t-partials (8 warps), then write fp16 g_attpv
    float* red2 = (float*)sm;   // [8 warps][32 s x 65 d-pad], warp stride 2084
#pragma unroll
    for (int mt = 0; mt < 2; mt++)
#pragma unroll
        for (int nd = 0; nd < 8; nd++)
#pragma unroll
            for (int e = 0; e < 4; e++) {
                int sl = mt * 16 + (lane >> 2) + ((e >> 1) << 3);
                int d = nd * 8 + (lane & 3) * 2 + (e & 1);
                red2[wn * 2084 + sl * 65 + d] = accpv[mt][nd][e];
            }
    __syncthreads();
    int b = bh >> 4, h = bh & 15;
    for (int i = tid; i < 1024; i += 256) {
        int sl = i >> 5, d = (i & 31) * 2;
        float v0 = 0.f, v1 = 0.f;
#pragma unroll
        for (int w = 0; w < 8; w++) {
            v0 += red2[w * 2084 + sl * 65 + d];
            v1 += red2[w * 2084 + sl * 65 + d + 1];
        }
        *(__half2*)&g_attpv[((size_t)(b * 1024 + s0 + sl)) * 1024 + h * 64 + d] =
            __floats2half2_rn(v0, v1);
    }
}

// ---------------- K6: attf = att_pv + W @ EV_s (pipelined ev stream) ----------------
__global__ __launch_bounds__(256) void k6_ev(const float* __restrict__ ev) {
    extern __shared__ char sm[];
    char *aF = sm, *bFh = sm + 17408;
    uint32_t aFu = smem_u32(aF), bFu = smem_u32(bFh);
    uint32_t brawu = smem_u32(sm + 35840);
    int s = blockIdx.x;
    const float* evs = ev + (size_t)s * 65536;
    float acc[1][4][4] = {};
    auto issueB = [&](int c) {
        uint32_t dst = brawu + (uint32_t)(c & 1) * 32768;
        const float* src = evs + (size_t)c * 8192;
#pragma unroll
        for (int i = threadIdx.x; i < 2048; i += 256)
            cp16(dst + (uint32_t)i * 16, src + i * 4);
        cp_commit();
    };
    issueB(0);
    for (int c = 0; c < 8; c++) {
        load_one<64, 128>(aF, g_wf + (size_t)s * 65536 + c * 128, 1024);
        if (c < 7) { issueB(c + 1); cp_wait<1>(); } else cp_wait<0>();
        __syncthreads();
        const float* bw = (const float*)(sm + 35840 + (c & 1) * 32768);
#pragma unroll
        for (int i = threadIdx.x; i < 2048; i += 256) {
            int r = i >> 4, cc = (i & 15) * 4;
            float4 v = *(const float4*)(bw + r * 64 + cc);
            HF4 Hh;
            Hh.b[0] = __float2half_rn(v.x); Hh.b[1] = __float2half_rn(v.y);
            Hh.b[2] = __float2half_rn(v.z); Hh.b[3] = __float2half_rn(v.w);
            *(uint2*)(bFh + (r * 72 + cc) * 2) = Hh.u;
        }
        __syncthreads();
        mma_chunk_h1<2, 1, 4, 136, 72, 8, true>(aFu, bFu, acc);
        __syncthreads();
    }
    int lane = threadIdx.x & 31, wid = threadIdx.x >> 5, wm = wid / 2, wn = wid % 2;
#pragma unroll
    for (int nt = 0; nt < 4; nt++)
#pragma unroll
        for (int hf = 0; hf < 2; hf++) {
            int bh = wm * 16 + (lane >> 2) + hf * 8;
            int d = wn * 32 + nt * 8 + (lane & 3) * 2;
            int b = bh >> 4, h = bh & 15;
            size_t o = ((size_t)(b * 1024 + s)) * 1024 + h * 64 + d;
            HF2 pv;
            pv.u = *(const uint32_t*)&g_attpv[o];
            HF2 P;
            P.b[0] = __float2half_rn(__half2float(pv.b[0]) + acc[0][nt][hf * 2]);
            P.b[1] = __float2half_rn(__half2float(pv.b[1]) + acc[0][nt][hf * 2 + 1]);
            *(uint32_t*)&g_attf[o] = P.u;
        }
}

// ---------------- G7: out = att @ Wp^T + bp (1 product, cp.async) ----------------
__global__ __launch_bounds__(256) void g7_out(const float* __restrict__ bp, float* __restrict__ out) {
    extern __shared__ char sm[];
    uint32_t smb = smem_u32(sm);
    constexpr int TS = 128 * 72 * 2;
    constexpr int STG = 2 * TS;
    int m0 = blockIdx.y * 128, n0 = blockIdx.x * 128;
    const __half* Bf = g_wtf + (size_t)3 * 1048576 + (size_t)n0 * 1024;
    float acc[4][4][4] = {};
    auto issue = [&](int c) {
        uint32_t b = smb + (uint32_t)(c & 1) * STG;
        cp_one<128, 64>(b, g_attf + (size_t)m0 * 1024 + c * 64, 1024);
        cp_one<128, 64>(b + TS, Bf + c * 64, 1024);
        cp_commit();
    };
    issue(0);
    for (int c = 0; c < 16; c++) {
        if (c < 15) { issue(c + 1); cp_wait<1>(); } else cp_wait<0>();
        __syncthreads();
        uint32_t b = smb + (uint32_t)(c & 1) * STG;
        mma_chunk_h1<4, 4, 4, 72, 72, 4, false>(b, b + TS, acc);
        __syncthreads();
    }
    int lane = threadIdx.x & 31, wid = threadIdx.x >> 5, wm = wid / 4, wn = wid % 4;
#pragma unroll
    for (int mt = 0; mt < 4; mt++)
#pragma unroll
        for (int nt = 0; nt < 4; nt++)
#pragma unroll
            for (int hf = 0; hf < 2; hf++) {
                int m = m0 + wm * 64 + mt * 16 + (lane >> 2) + hf * 8;
                int n = n0 + wn * 32 + nt * 8 + (lane & 3) * 2;
                float2 bb = *(const float2*)&bp[n];
                float2 vv;
                vv.x = acc[mt][nt][hf * 2] + bb.x;
                vv.y = acc[mt][nt][hf * 2 + 1] + bb.y;
                *(float2*)&out[(size_t)m * 1024 + n] = vv;
            }
}

// ---------------- launch ----------------
extern "C" void kernel_launch(void* const* d_in, const int* in_sizes, int n_in,
                              void* d_out, int out_size) {
    const float* queries     = (const float*)d_in[0];
    const float* keys        = (const float*)d_in[1];
    const float* values      = (const float*)d_in[2];
    const float* edges_key   = (const float*)d_in[3];
    const float* edges_value = (const float*)d_in[4];
    const float* attn_bias   = (const float*)d_in[5];
    const float* Wq = (const float*)d_in[6];  const float* bq = (const float*)d_in[7];
    const float* Wk = (const float*)d_in[8];  const float* bk = (const float*)d_in[9];
    const float* Wv = (const float*)d_in[10]; const float* bv = (const float*)d_in[11];
    const float* Wp = (const float*)d_in[12]; const float* bp = (const float*)d_in[13];

    cudaFuncSetAttribute(g1_qkv,  cudaFuncAttributeMaxDynamicSharedMemorySize, 73728);
    cudaFuncSetAttribute(k3_edge, cudaFuncAttributeMaxDynamicSharedMemorySize, 27648);
    cudaFuncSetAttribute(g2s,     cudaFuncAttributeMaxDynamicSharedMemorySize, 67584);
    cudaFuncSetAttribute(k6_ev,   cudaFuncAttributeMaxDynamicSharedMemorySize, 101376);
    cudaFuncSetAttribute(g7_out,  cudaFuncAttributeMaxDynamicSharedMemorySize, 73728);

    c0_wt<<<dim3(32, 32, 4), 256>>>(Wq, Wk, Wv, Wp);
    c1_x<<<dim3(4096, 3), 256>>>(queries, keys, values);
    g1_qkv<<<dim3(8, 32, 3), 256, 73728>>>(bq, bk, bv);
    k3_edge<<<dim3(4, 1024), 256, 27648>>>(edges_key);
    g2s<<<dim3(32, 64), 256, 67584>>>(attn_bias);
    k6_ev<<<1024, 256, 101376>>>(edges_value);
    g7_out<<<dim3(8, 32), 256, 73728>>>(bp, (float*)d_out);
}

// round 16
// speedup vs baseline: 1.0593x; 1.0041x over previous
#include <cuda_runtime.h>
#include <cuda_bf16.h>
#include <cuda_fp16.h>
#include <cstdint>

// B=4, S=1024, E=1024, H=16, D=64, BH=64.
// R15 base (PV fused in g2s, fp16 attpv). Delta: k3 uses cp.async-pipelined
// raw ek chunks (k6 pattern), 4 t-chunks per block, grid 2048.

#define DI __device__ __forceinline__

// ---------------- device scratch ----------------
__device__ __align__(128) __half g_we[67108864];                // fp16 edge logits [s][bh][t]
__device__ __align__(128) __half g_wf[67108864];                // fp16 softmax weights [s][bh][t]
__device__ __align__(128) __half g_attpv[4194304];              // fp16 PV partial att [b*s][h*d]
__device__ __align__(128) __half g_xf[3*4194304];               // X fp16 [z][m][k]
__device__ __align__(128) __half g_wtf[4*1048576];              // W^T fp16 [mat][n][k]
__device__ __align__(128) __half g_qf[4194304];                 // [bh][s][d] scaled q
__device__ __align__(128) __half g_kf[4194304];                 // [bh][t][d]
__device__ __align__(128) __half g_vf[4194304];                 // [bh][s][d]
__device__ __align__(128) __half g_attf[4194304];               // final att fp16 [b*s][h*d]

// ---------------- helpers ----------------
union HF2 { __half b[2]; uint32_t u; };
union HF4 { __half b[4]; uint2 u; };

DI uint32_t smem_u32(const void* p) {
    uint32_t a;
    asm("{ .reg .u64 t; cvta.to.shared.u64 t, %1; cvt.u32.u64 %0, t; }" : "=r"(a) : "l"(p));
    return a;
}
DI void ldsm4(uint32_t* r, uint32_t a) {
    asm volatile("ldmatrix.sync.aligned.m8n8.x4.shared.b16 {%0,%1,%2,%3}, [%4];"
        : "=r"(r[0]), "=r"(r[1]), "=r"(r[2]), "=r"(r[3]) : "r"(a));
}
DI void ldsm4t(uint32_t* r, uint32_t a) {
    asm volatile("ldmatrix.sync.aligned.m8n8.x4.trans.shared.b16 {%0,%1,%2,%3}, [%4];"
        : "=r"(r[0]), "=r"(r[1]), "=r"(r[2]), "=r"(r[3]) : "r"(a));
}
DI void mma16816h(float* d, const uint32_t* a, const uint32_t* b) {
    asm volatile("mma.sync.aligned.m16n8k16.row.col.f32.f16.f16.f32 "
        "{%0,%1,%2,%3}, {%4,%5,%6,%7}, {%8,%9}, {%0,%1,%2,%3};"
        : "+f"(d[0]), "+f"(d[1]), "+f"(d[2]), "+f"(d[3])
        : "r"(a[0]), "r"(a[1]), "r"(a[2]), "r"(a[3]), "r"(b[0]), "r"(b[1]));
}
DI void cp16(uint32_t d, const void* s) {
    asm volatile("cp.async.cg.shared.global [%0], [%1], 16;" :: "r"(d), "l"(s));
}
DI void cp_commit() { asm volatile("cp.async.commit_group;" ::: "memory"); }
template <int N> DI void cp_wait() {
    asm volatile("cp.async.wait_group %0;" :: "n"(N) : "memory");
}

template <int ROWS, int KC, typename T>
DI void cp_one(uint32_t s, const T* G, size_t ldg) {
    constexpr int SA = KC + 8;
#pragma unroll
    for (int i = threadIdx.x; i < ROWS * KC / 8; i += 256) {
        int r = i / (KC / 8), c = (i % (KC / 8)) * 8;
        cp16(s + (uint32_t)(r * SA + c) * 2, G + (size_t)r * ldg + c);
    }
}
template <int ROWS, int KC, typename T>
DI void load_one(char* s, const T* G, size_t ldg) {
    constexpr int SA = KC + 8;
#pragma unroll 4
    for (int i = threadIdx.x; i < ROWS * KC / 8; i += 256) {
        int r = i / (KC / 8), c = (i % (KC / 8)) * 8;
        *(uint4*)(s + (r * SA + c) * 2) = *(const uint4*)(G + (size_t)r * ldg + c);
    }
}
template <int ROWS, int KC>
DI void load_cvt_h(char* s, const float* G, size_t ldg) {
    constexpr int SA = KC + 8;
#pragma unroll 4
    for (int i = threadIdx.x; i < ROWS * KC / 4; i += 256) {
        int r = i / (KC / 4), c = (i % (KC / 4)) * 4;
        float4 v = *(const float4*)(G + (size_t)r * ldg + c);
        HF4 Hh;
        Hh.b[0] = __float2half_rn(v.x); Hh.b[1] = __float2half_rn(v.y);
        Hh.b[2] = __float2half_rn(v.z); Hh.b[3] = __float2half_rn(v.w);
        *(uint2*)(s + (r * SA + c) * 2) = Hh.u;
    }
}

// fp16 chunk: A single, B single -> 1 product
template <int WN, int MT, int NT, int SA, int SB, int KSTEPS, bool BT>
DI void mma_chunk_h1(uint32_t aF, uint32_t bF, float (&acc)[MT][NT][4]) {
    int lane = threadIdx.x & 31, wid = threadIdx.x >> 5;
    int wm = wid / WN, wn = wid % WN;
#pragma unroll
    for (int kk = 0; kk < KSTEPS; kk++) {
        uint32_t af[MT][4], bf[NT][2];
#pragma unroll
        for (int mt = 0; mt < MT; mt++) {
            uint32_t off = (uint32_t)(((wm * MT * 16 + mt * 16 + (lane & 15)) * SA
                                       + kk * 16 + (lane >> 4) * 8) * 2);
            ldsm4(af[mt], aF + off);
        }
#pragma unroll
        for (int nt = 0; nt < NT; nt += 2) {
            uint32_t off;
            if (BT)
                off = (uint32_t)(((kk * 16 + (lane & 15)) * SB
                                  + wn * NT * 8 + nt * 8 + (lane >> 4) * 8) * 2);
            else
                off = (uint32_t)(((wn * NT * 8 + nt * 8 + ((lane >> 4) << 3) + (lane & 7)) * SB
                                  + kk * 16 + (((lane >> 3) & 1) << 3)) * 2);
            uint32_t r[4];
            if (BT) ldsm4t(r, bF + off); else ldsm4(r, bF + off);
            bf[nt][0] = r[0]; bf[nt][1] = r[1]; bf[nt + 1][0] = r[2]; bf[nt + 1][1] = r[3];
        }
#pragma unroll
        for (int mt = 0; mt < MT; mt++)
#pragma unroll
            for (int nt = 0; nt < NT; nt++)
                mma16816h(acc[mt][nt], af[mt], bf[nt]);
    }
}

// ---------------- conversion kernels ----------------
__global__ __launch_bounds__(256) void c0_wt(const float* Wq, const float* Wk,
                                             const float* Wv, const float* Wp) {
    __shared__ float smt[32][33];
    int mat = blockIdx.z;
    const float* W = mat == 0 ? Wq : mat == 1 ? Wk : mat == 2 ? Wv : Wp;
    int nblk = blockIdx.x * 32, kblk = blockIdx.y * 32;
    for (int i = threadIdx.x; i < 1024; i += 256) {
        int r = i >> 5, c = i & 31;
        smt[r][c] = W[(size_t)(kblk + r) * 1024 + nblk + c];
    }
    __syncthreads();
    for (int i = threadIdx.x; i < 1024; i += 256) {
        int n = i >> 5, k = i & 31;
        size_t o = (size_t)mat * 1048576 + (size_t)(nblk + n) * 1024 + kblk + k;
        g_wtf[o] = __float2half_rn(smt[k][n]);
    }
}
__global__ __launch_bounds__(256) void c1_x(const float* q, const float* k, const float* v) {
    int z = blockIdx.y;
    const float* X = z == 0 ? q : z == 1 ? k : v;
    size_t idx = ((size_t)blockIdx.x * 256 + threadIdx.x) * 4;
    float4 t = *(const float4*)&X[idx];
    HF4 Hh;
    Hh.b[0] = __float2half_rn(t.x); Hh.b[1] = __float2half_rn(t.y);
    Hh.b[2] = __float2half_rn(t.z); Hh.b[3] = __float2half_rn(t.w);
    *(uint2*)&g_xf[(size_t)z * 4194304 + idx] = Hh.u;
}

// ---------------- G1: q/k/v = X @ W^T + b (1 product, cp.async) ----------------
__global__ __launch_bounds__(256) void g1_qkv(const float* bq, const float* bk, const float* bv) {
    extern __shared__ char sm[];
    uint32_t smb = smem_u32(sm);
    constexpr int TS = 128 * 72 * 2;
    constexpr int STG = 2 * TS;
    int z = blockIdx.z, m0 = blockIdx.y * 128, n0 = blockIdx.x * 128;
    const __half* Af = g_xf + (size_t)z * 4194304 + (size_t)m0 * 1024;
    const __half* Bf = g_wtf + (size_t)z * 1048576 + (size_t)n0 * 1024;
    float acc[4][4][4] = {};
    auto issue = [&](int c) {
        uint32_t b = smb + (uint32_t)(c & 1) * STG;
        cp_one<128, 64>(b, Af + c * 64, 1024);
        cp_one<128, 64>(b + TS, Bf + c * 64, 1024);
        cp_commit();
    };
    issue(0);
    for (int c = 0; c < 16; c++) {
        if (c < 15) { issue(c + 1); cp_wait<1>(); } else cp_wait<0>();
        __syncthreads();
        uint32_t b = smb + (uint32_t)(c & 1) * STG;
        mma_chunk_h1<4, 4, 4, 72, 72, 4, false>(b, b + TS, acc);
        __syncthreads();
    }
    const float* bias = z == 0 ? bq : z == 1 ? bk : bv;
    float sc = z == 0 ? 0.125f : 1.f;
    __half* dst = z == 0 ? g_qf : z == 1 ? g_kf : g_vf;
    int lane = threadIdx.x & 31, wid = threadIdx.x >> 5, wm = wid / 4, wn = wid % 4;
#pragma unroll
    for (int mt = 0; mt < 4; mt++)
#pragma unroll
        for (int nt = 0; nt < 4; nt++)
#pragma unroll
            for (int hf = 0; hf < 2; hf++) {
                int m = m0 + wm * 64 + mt * 16 + (lane >> 2) + hf * 8;
                int n = n0 + wn * 32 + nt * 8 + (lane & 3) * 2;
                float v0 = (acc[mt][nt][hf * 2] + bias[n]) * sc;
                float v1 = (acc[mt][nt][hf * 2 + 1] + bias[n + 1]) * sc;
                int b = m >> 10, s = m & 1023, h = n >> 6, d = n & 63;
                size_t o = ((size_t)((b << 4) + h) * 1024 + s) * 64 + d;
                HF2 P;
                P.b[0] = __float2half_rn(v0); P.b[1] = __float2half_rn(v1);
                *(uint32_t*)&dst[o] = P.u;
            }
}

// ---------------- K3: g_we[s][bh][t] = fp16 edge-key logits ----------------
// 4 t-chunks per block, cp.async raw fp32 ek double-buffer (k6 pattern).
// smem: q 9216 | conv 18432 | raw 2x32768 @ 27648. total 93184.
__global__ __launch_bounds__(256) void k3_edge(const float* __restrict__ ek) {
    extern __shared__ char sm[];
    char *aF = sm, *bF = sm + 9216;
    uint32_t aFu = smem_u32(aF), bFu = smem_u32(bF);
    uint32_t brawu = smem_u32(sm + 27648);
    int s = blockIdx.y, c0 = blockIdx.x * 4;   // 4 chunks of 128 t
    int lane = threadIdx.x & 31, wid = threadIdx.x >> 5, wm = wid / 4, wn = wid % 4;
    size_t sbase = (size_t)s * 65536;
    const float* eks = ek + (size_t)s * 65536;

    auto issueRaw = [&](int c) {
        uint32_t dst = brawu + (uint32_t)(c & 1) * 32768;
        const float* src = eks + (size_t)(c0 + c) * 8192;   // contiguous 32KB
#pragma unroll
        for (int i = threadIdx.x; i < 2048; i += 256)
            cp16(dst + (uint32_t)i * 16, src + i * 4);
        cp_commit();
    };
    issueRaw(0);
    load_one<64, 64>(aF, g_qf + (size_t)s * 64, 65536);
    for (int c = 0; c < 4; c++) {
        if (c < 3) { issueRaw(c + 1); cp_wait<1>(); } else cp_wait<0>();
        __syncthreads();
        // convert raw fp32 [128 t][64 d] -> fp16 conv tile (stride 72)
        const float* bw = (const float*)(sm + 27648 + (c & 1) * 32768);
#pragma unroll
        for (int i = threadIdx.x; i < 2048; i += 256) {
            int r = i >> 4, cc = (i & 15) * 4;
            float4 v = *(const float4*)(bw + r * 64 + cc);
            HF4 Hh;
            Hh.b[0] = __float2half_rn(v.x); Hh.b[1] = __float2half_rn(v.y);
            Hh.b[2] = __float2half_rn(v.z); Hh.b[3] = __float2half_rn(v.w);
            *(uint2*)(bF + (r * 72 + cc) * 2) = Hh.u;
        }
        __syncthreads();
        float acc[2][4][4] = {};
        mma_chunk_h1<4, 2, 4, 72, 72, 4, false>(aFu, bFu, acc);
        int t0 = (c0 + c) * 128;
#pragma unroll
        for (int mt = 0; mt < 2; mt++)
#pragma unroll
            for (int nt = 0; nt < 4; nt++)
#pragma unroll
                for (int hf = 0; hf < 2; hf++) {
                    int bh = wm * 32 + mt * 16 + (lane >> 2) + hf * 8;
                    int t = t0 + wn * 32 + nt * 8 + (lane & 3) * 2;
                    HF2 P;
                    P.b[0] = __float2half_rn(acc[mt][nt][hf * 2]);
                    P.b[1] = __float2half_rn(acc[mt][nt][hf * 2 + 1]);
                    *(uint32_t*)&g_we[sbase + (size_t)bh * 1024 + t] = P.u;
                }
        __syncthreads();
    }
}

// ---------- G2S: content+bias+edge logits, softmax, fp16 w, FUSED PV ----------
__global__ __launch_bounds__(256) void g2s(const float* __restrict__ attn_bias) {
    extern __shared__ char sm[];
    __shared__ float red[8][32];
    __shared__ float redc[32];
    constexpr int KTS = 128 * 72 * 2;
    uint32_t smb = smem_u32(sm);
    uint32_t qFu = smb;
    int s0 = blockIdx.x * 32, bh = blockIdx.y;
    int tid = threadIdx.x, lane = tid & 31, wn = tid >> 5;

    auto issueK = [&](int it) {
        uint32_t b = smb + 4608 + (uint32_t)(it & 1) * KTS;
        cp_one<128, 64>(b, g_kf + (size_t)bh * 65536 + (size_t)it * 8192, 64);
        cp_commit();
    };
    issueK(0);
    load_one<32, 64>(sm, g_qf + (size_t)bh * 65536 + (size_t)s0 * 64, 64);

    float acc[2][16][4] = {};
    for (int it = 0; it < 8; it++) {
        if (it < 7) { issueK(it + 1); cp_wait<1>(); } else cp_wait<0>();
        __syncthreads();
        uint32_t kFu = smb + 4608 + (uint32_t)(it & 1) * KTS;
#pragma unroll
        for (int kk = 0; kk < 4; kk++) {
            uint32_t ah[2][4], bf2[2][2];
#pragma unroll
            for (int mt = 0; mt < 2; mt++) {
                uint32_t off = (uint32_t)(((mt * 16 + (lane & 15)) * 72
                                           + kk * 16 + (lane >> 4) * 8) * 2);
                ldsm4(ah[mt], qFu + off);
            }
            {
                uint32_t off = (uint32_t)(((wn * 16 + ((lane >> 4) << 3) + (lane & 7)) * 72
                                           + kk * 16 + (((lane >> 3) & 1) << 3)) * 2);
                uint32_t r[4];
                ldsm4(r, kFu + off);
                bf2[0][0] = r[0]; bf2[0][1] = r[1]; bf2[1][0] = r[2]; bf2[1][1] = r[3];
            }
#pragma unroll
            for (int mt = 0; mt < 2; mt++)
#pragma unroll
                for (int ntl = 0; ntl < 2; ntl++)
                    mma16816h(acc[mt][it * 2 + ntl], ah[mt], bf2[ntl]);
        }
        __syncthreads();
    }

    size_t bbase = (size_t)bh * 1048576;
#pragma unroll
    for (int mt = 0; mt < 2; mt++)
#pragma unroll
        for (int ntg = 0; ntg < 16; ntg++) {
            int sl = mt * 16 + (lane >> 2);
            int t = (ntg >> 1) * 128 + wn * 16 + (ntg & 1) * 8 + (lane & 3) * 2;
            float2 b0 = *(const float2*)&attn_bias[bbase + (size_t)(s0 + sl) * 1024 + t];
            float2 b1 = *(const float2*)&attn_bias[bbase + (size_t)(s0 + sl + 8) * 1024 + t];
            HF2 e0, e1;
            e0.u = *(const uint32_t*)&g_we[(size_t)(s0 + sl) * 65536 + (size_t)bh * 1024 + t];
            e1.u = *(const uint32_t*)&g_we[(size_t)(s0 + sl + 8) * 65536 + (size_t)bh * 1024 + t];
            acc[mt][ntg][0] += b0.x + __half2float(e0.b[0]);
            acc[mt][ntg][1] += b0.y + __half2float(e0.b[1]);
            acc[mt][ntg][2] += b1.x + __half2float(e1.b[0]);
            acc[mt][ntg][3] += b1.y + __half2float(e1.b[1]);
        }

    float rv[4];
#pragma unroll
    for (int r = 0; r < 4; r++) rv[r] = -1e30f;
#pragma unroll
    for (int mt = 0; mt < 2; mt++)
#pragma unroll
        for (int ntg = 0; ntg < 16; ntg++)
#pragma unroll
            for (int e = 0; e < 4; e++) {
                int r = mt * 2 + (e >> 1);
                rv[r] = fmaxf(rv[r], acc[mt][ntg][e]);
            }
#pragma unroll
    for (int r = 0; r < 4; r++) {
        rv[r] = fmaxf(rv[r], __shfl_xor_sync(~0u, rv[r], 1));
        rv[r] = fmaxf(rv[r], __shfl_xor_sync(~0u, rv[r], 2));
    }
    if ((lane & 3) == 0)
#pragma unroll
        for (int r = 0; r < 4; r++)
            red[wn][(r >> 1) * 16 + (lane >> 2) + (r & 1) * 8] = rv[r];
    __syncthreads();
    if (tid < 32) {
        float m = red[0][tid];
#pragma unroll
        for (int w = 1; w < 8; w++) m = fmaxf(m, red[w][tid]);
        redc[tid] = m;
    }
    __syncthreads();
    float rmax[4];
#pragma unroll
    for (int r = 0; r < 4; r++) rmax[r] = redc[(r >> 1) * 16 + (lane >> 2) + (r & 1) * 8];
    __syncthreads();

#pragma unroll
    for (int r = 0; r < 4; r++) rv[r] = 0.f;
#pragma unroll
    for (int mt = 0; mt < 2; mt++)
#pragma unroll
        for (int ntg = 0; ntg < 16; ntg++)
#pragma unroll
            for (int e = 0; e < 4; e++) {
                int r = mt * 2 + (e >> 1);
                float v = __expf(acc[mt][ntg][e] - rmax[r]);
                acc[mt][ntg][e] = v;
                rv[r] += v;
            }
#pragma unroll
    for (int r = 0; r < 4; r++) {
        rv[r] += __shfl_xor_sync(~0u, rv[r], 1);
        rv[r] += __shfl_xor_sync(~0u, rv[r], 2);
    }
    if ((lane & 3) == 0)
#pragma unroll
        for (int r = 0; r < 4; r++)
            red[wn][(r >> 1) * 16 + (lane >> 2) + (r & 1) * 8] = rv[r];
    __syncthreads();
    if (tid < 32) {
        float sval = red[0][tid];
#pragma unroll
        for (int w = 1; w < 8; w++) sval += red[w][tid];
        redc[tid] = 1.0f / sval;
    }
    __syncthreads();
    float rinv[4];
#pragma unroll
    for (int r = 0; r < 4; r++) rinv[r] = redc[(r >> 1) * 16 + (lane >> 2) + (r & 1) * 8];
    __syncthreads();

    uint32_t wh[2][16][2];
#pragma unroll
    for (int mt = 0; mt < 2; mt++)
#pragma unroll
        for (int ntg = 0; ntg < 16; ntg++) {
            HF2 p0, p1;
            *(__half2*)&p0 = __floats2half2_rn(acc[mt][ntg][0] * rinv[mt * 2],
                                               acc[mt][ntg][1] * rinv[mt * 2]);
            *(__half2*)&p1 = __floats2half2_rn(acc[mt][ntg][2] * rinv[mt * 2 + 1],
                                               acc[mt][ntg][3] * rinv[mt * 2 + 1]);
            wh[mt][ntg][0] = p0.u;
            wh[mt][ntg][1] = p1.u;
        }

    __half* stg = (__half*)sm;   // 32 x 1040
#pragma unroll
    for (int mt = 0; mt < 2; mt++)
#pragma unroll
        for (int ntg = 0; ntg < 16; ntg++) {
            int sl = mt * 16 + (lane >> 2);
            int t = (ntg >> 1) * 128 + wn * 16 + (ntg & 1) * 8 + (lane & 3) * 2;
            *(uint32_t*)&stg[sl * 1040 + t] = wh[mt][ntg][0];
            *(uint32_t*)&stg[(sl + 8) * 1040 + t] = wh[mt][ntg][1];
        }
    __syncthreads();
    for (int i = tid; i < 32 * 128; i += 256) {
        int rr = i >> 7, cc = (i & 127) * 8;
        *(uint4*)&g_wf[(size_t)(s0 + rr) * 65536 + (size_t)bh * 1024 + cc] =
            *(const uint4*)&stg[rr * 1040 + cc];
    }
    __syncthreads();

    // ---- fused PV: att_pv = w @ V ----
    auto issueV = [&](int p) {
        uint32_t b = smb + (uint32_t)(p & 1) * 18432;
        cp_one<128, 64>(b, g_vf + (size_t)bh * 65536 + (size_t)p * 8192, 64);
        cp_commit();
    };
    issueV(0);
    float accpv[2][8][4] = {};
    for (int p = 0; p < 8; p++) {
        if (p < 7) { issueV(p + 1); cp_wait<1>(); } else cp_wait<0>();
        __syncthreads();
        uint32_t vb = smb + (uint32_t)(p & 1) * 18432;
        uint32_t bf[8][2];
#pragma unroll
        for (int nt = 0; nt < 8; nt += 2) {
            uint32_t off = (uint32_t)(((wn * 16 + (lane & 15)) * 72
                                       + nt * 8 + (lane >> 4) * 8) * 2);
            uint32_t r[4];
            ldsm4t(r, vb + off);
            bf[nt][0] = r[0]; bf[nt][1] = r[1]; bf[nt + 1][0] = r[2]; bf[nt + 1][1] = r[3];
        }
#pragma unroll
        for (int mt = 0; mt < 2; mt++) {
            uint32_t aR[4] = {wh[mt][2 * p][0], wh[mt][2 * p][1],
                              wh[mt][2 * p + 1][0], wh[mt][2 * p + 1][1]};
#pragma unroll
            for (int nd = 0; nd < 8; nd++)
                mma16816h(accpv[mt][nd], aR, bf[nd]);
        }
        __syncthreads();
    }

    float* red2 = (float*)sm;   // [8 warps][32 s x 65 d-pad]
#pragma unroll
    for (int mt = 0; mt < 2; mt++)
#pragma unroll
        for (int nd = 0; nd < 8; nd++)
#pragma unroll
            for (int e = 0; e < 4; e++) {
                int sl = mt * 16 + (lane >> 2) + ((e >> 1) << 3);
                int d = nd * 8 + (lane & 3) * 2 + (e & 1);
                red2[wn * 2084 + sl * 65 + d] = accpv[mt][nd][e];
            }
    __syncthreads();
    int b = bh >> 4, h = bh & 15;
    for (int i = tid; i < 1024; i += 256) {
        int sl = i >> 5, d = (i & 31) * 2;
        float v0 = 0.f, v1 = 0.f;
#pragma unroll
        for (int w = 0; w < 8; w++) {
            v0 += red2[w * 2084 + sl * 65 + d];
            v1 += red2[w * 2084 + sl * 65 + d + 1];
        }
        *(__half2*)&g_attpv[((size_t)(b * 1024 + s0 + sl)) * 1024 + h * 64 + d] =
            __floats2half2_rn(v0, v1);
    }
}

// ---------------- K6: attf = att_pv + W @ EV_s (pipelined ev stream) ----------------
__global__ __launch_bounds__(256) void k6_ev(const float* __restrict__ ev) {
    extern __shared__ char sm[];
    char *aF = sm, *bFh = sm + 17408;
    uint32_t aFu = smem_u32(aF), bFu = smem_u32(bFh);
    uint32_t brawu = smem_u32(sm + 35840);
    int s = blockIdx.x;
    const float* evs = ev + (size_t)s * 65536;
    float acc[1][4][4] = {};
    auto issueB = [&](int c) {
        uint32_t dst = brawu + (uint32_t)(c & 1) * 32768;
        const float* src = evs + (size_t)c * 8192;
#pragma unroll
        for (int i = threadIdx.x; i < 2048; i += 256)
            cp16(dst + (uint32_t)i * 16, src + i * 4);
        cp_commit();
    };
    issueB(0);
    for (int c = 0; c < 8; c++) {
        load_one<64, 128>(aF, g_wf + (size_t)s * 65536 + c * 128, 1024);
        if (c < 7) { issueB(c + 1); cp_wait<1>(); } else cp_wait<0>();
        __syncthreads();
        const float* bw = (const float*)(sm + 35840 + (c & 1) * 32768);
#pragma unroll
        for (int i = threadIdx.x; i < 2048; i += 256) {
            int r = i >> 4, cc = (i & 15) * 4;
            float4 v = *(const float4*)(bw + r * 64 + cc);
            HF4 Hh;
            Hh.b[0] = __float2half_rn(v.x); Hh.b[1] = __float2half_rn(v.y);
            Hh.b[2] = __float2half_rn(v.z); Hh.b[3] = __float2half_rn(v.w);
            *(uint2*)(bFh + (r * 72 + cc) * 2) = Hh.u;
        }
        __syncthreads();
        mma_chunk_h1<2, 1, 4, 136, 72, 8, true>(aFu, bFu, acc);
        __syncthreads();
    }
    int lane = threadIdx.x & 31, wid = threadIdx.x >> 5, wm = wid / 2, wn = wid % 2;
#pragma unroll
    for (int nt = 0; nt < 4; nt++)
#pragma unroll
        for (int hf = 0; hf < 2; hf++) {
            int bh = wm * 16 + (lane >> 2) + hf * 8;
            int d = wn * 32 + nt * 8 + (lane & 3) * 2;
            int b = bh >> 4, h = bh & 15;
            size_t o = ((size_t)(b * 1024 + s)) * 1024 + h * 64 + d;
            HF2 pv;
            pv.u = *(const uint32_t*)&g_attpv[o];
            HF2 P;
            P.b[0] = __float2half_rn(__half2float(pv.b[0]) + acc[0][nt][hf * 2]);
            P.b[1] = __float2half_rn(__half2float(pv.b[1]) + acc[0][nt][hf * 2 + 1]);
            *(uint32_t*)&g_attf[o] = P.u;
        }
}

// ---------------- G7: out = att @ Wp^T + bp (1 product, cp.async) ----------------
__global__ __launch_bounds__(256) void g7_out(const float* __restrict__ bp, float* __restrict__ out) {
    extern __shared__ char sm[];
    uint32_t smb = smem_u32(sm);
    constexpr int TS = 128 * 72 * 2;
    constexpr int STG = 2 * TS;
    int m0 = blockIdx.y * 128, n0 = blockIdx.x * 128;
    const __half* Bf = g_wtf + (size_t)3 * 1048576 + (size_t)n0 * 1024;
    float acc[4][4][4] = {};
    auto issue = [&](int c) {
        uint32_t b = smb + (uint32_t)(c & 1) * STG;
        cp_one<128, 64>(b, g_attf + (size_t)m0 * 1024 + c * 64, 1024);
        cp_one<128, 64>(b + TS, Bf + c * 64, 1024);
        cp_commit();
    };
    issue(0);
    for (int c = 0; c < 16; c++) {
        if (c < 15) { issue(c + 1); cp_wait<1>(); } else cp_wait<0>();
        __syncthreads();
        uint32_t b = smb + (uint32_t)(c & 1) * STG;
        mma_chunk_h1<4, 4, 4, 72, 72, 4, false>(b, b + TS, acc);
        __syncthreads();
    }
    int lane = threadIdx.x & 31, wid = threadIdx.x >> 5, wm = wid / 4, wn = wid % 4;
#pragma unroll
    for (int mt = 0; mt < 4; mt++)
#pragma unroll
        for (int nt = 0; nt < 4; nt++)
#pragma unroll
            for (int hf = 0; hf < 2; hf++) {
                int m = m0 + wm * 64 + mt * 16 + (lane >> 2) + hf * 8;
                int n = n0 + wn * 32 + nt * 8 + (lane & 3) * 2;
                float2 bb = *(const float2*)&bp[n];
                float2 vv;
                vv.x = acc[mt][nt][hf * 2] + bb.x;
                vv.y = acc[mt][nt][hf * 2 + 1] + bb.y;
                *(float2*)&out[(size_t)m * 1024 + n] = vv;
            }
}

// ---------------- launch ----------------
extern "C" void kernel_launch(void* const* d_in, const int* in_sizes, int n_in,
                              void* d_out, int out_size) {
    const float* queries     = (const float*)d_in[0];
    const float* keys        = (const float*)d_in[1];
    const float* values      = (const float*)d_in[2];
    const float* edges_key   = (const float*)d_in[3];
    const float* edges_value = (const float*)d_in[4];
    const float* attn_bias   = (const float*)d_in[5];
    const float* Wq = (const float*)d_in[6];  const float* bq = (const float*)d_in[7];
    const float* Wk = (const float*)d_in[8];  const float* bk = (const float*)d_in[9];
    const float* Wv = (const float*)d_in[10]; const float* bv = (const float*)d_in[11];
    const float* Wp = (const float*)d_in[12]; const float* bp = (const float*)d_in[13];

    cudaFuncSetAttribute(g1_qkv,  cudaFuncAttributeMaxDynamicSharedMemorySize, 73728);
    cudaFuncSetAttribute(k3_edge, cudaFuncAttributeMaxDynamicSharedMemorySize, 93184);
    cudaFuncSetAttribute(g2s,     cudaFuncAttributeMaxDynamicSharedMemorySize, 67584);
    cudaFuncSetAttribute(k6_ev,   cudaFuncAttributeMaxDynamicSharedMemorySize, 101376);
    cudaFuncSetAttribute(g7_out,  cudaFuncAttributeMaxDynamicSharedMemorySize, 73728);

    c0_wt<<<dim3(32, 32, 4), 256>>>(Wq, Wk, Wv, Wp);
    c1_x<<<dim3(4096, 3), 256>>>(queries, keys, values);
    g1_qkv<<<dim3(8, 32, 3), 256, 73728>>>(bq, bk, bv);
    k3_edge<<<dim3(2, 1024), 256, 93184>>>(edges_key);
    g2s<<<dim3(32, 64), 256, 67584>>>(attn_bias);
    k6_ev<<<1024, 256, 101376>>>(edges_value);
    g7_out<<<dim3(8, 32), 256, 73728>>>(bp, (float*)d_out);
}